// round 10
// baseline (speedup 1.0000x reference)
#include <cuda_runtime.h>
#include <cuda_bf16.h>
#include <math.h>
#include <stdint.h>

// ---------------- problem constants ----------------
#define B_    16
#define T_    4000
#define GRUH  256
#define H1_   128
#define H2_   64
#define N_    320000          // T_ * HOP(80)
#define M_    (B_ * T_)       // 64000 tokens

// ---------------- device scratch ----------------
__device__ float g_ratio[M_];
__device__ int   g_max_out_i;
__device__ int   g_max_enh_i;

// =====================================================================
// helpers
// =====================================================================
__device__ __forceinline__ uint32_t pack_bf16x2(__nv_bfloat16 a, __nv_bfloat16 b) {
    return (uint32_t)__bfloat16_as_ushort(a) | ((uint32_t)__bfloat16_as_ushort(b) << 16);
}
__device__ __forceinline__ void split2(float v0, float v1, uint32_t& hi, uint32_t& lo) {
    __nv_bfloat16 h0 = __float2bfloat16_rn(v0);
    __nv_bfloat16 h1 = __float2bfloat16_rn(v1);
    float l0 = v0 - __bfloat162float(h0);
    float l1 = v1 - __bfloat162float(h1);
    hi = pack_bf16x2(h0, h1);
    lo = pack_bf16x2(__float2bfloat16_rn(l0), __float2bfloat16_rn(l1));
}
// m16n8k16 bf16 MMA, f32 accumulate (portable PTX, sm_80+)
__device__ __forceinline__ void mma_bf16_(float c[4], const uint32_t a[4],
                                          uint32_t b0, uint32_t b1) {
    asm volatile(
        "mma.sync.aligned.m16n8k16.row.col.f32.bf16.bf16.f32 "
        "{%0,%1,%2,%3}, {%4,%5,%6,%7}, {%8,%9}, {%0,%1,%2,%3};"
        : "+f"(c[0]), "+f"(c[1]), "+f"(c[2]), "+f"(c[3])
        : "r"(a[0]), "r"(a[1]), "r"(a[2]), "r"(a[3]), "r"(b0), "r"(b1));
}
#define MMA(c, a, b0, b1) mma_bf16_(c, a, b0, b1)

// =====================================================================
// Kernel A: fused split-bf16 MLP via mma.sync  ->  ratio[m]
//   256 tokens/CTA, 250 CTAs, 1024 threads (32 warps, 8/SMSP).
//   GEMM1: warp = one m16 tile (16 rows) x 64 cols (N-half).
//   GEMM2: warp = one m16 tile x 32 cols (N-half of 64), pair-reduced
//   through small smem p-buffers for the final w3 dot.
// =====================================================================
#define TOK 256

#define W1_GSTRIDE 68
#define W2_GSTRIDE 36
#define H1_WSTRIDE 68

#define SO_W2Q  0
#define SO_B1   36864
#define SO_B2   37376
#define SO_W3   37632
#define SO_SC   37888
#define SO_W1Q  38016
#define SO_H1H  38016
#define SO_H1L  107648
#define SO_PB0  177280          // 256 f partial p (nhalf 0)
#define SO_PB1  178304          // 256 f partial p (nhalf 1)
#define MLP_SMEM 179328

__global__ __launch_bounds__(1024, 1)
void mlp_mma_kernel(const float* __restrict__ X,
                    const float* __restrict__ W1, const float* __restrict__ b1,
                    const float* __restrict__ a1p,
                    const float* __restrict__ W2, const float* __restrict__ b2,
                    const float* __restrict__ a2p,
                    const float* __restrict__ W3, const float* __restrict__ b3)
{
    extern __shared__ char sm[];
    const int tid  = threadIdx.x;
    const int wid  = tid >> 5;    // 0..31
    const int lane = tid & 31;
    const int grp  = lane >> 2;   // 0..7
    const int tig  = lane & 3;    // 0..3
    const int m0   = blockIdx.x * TOK;

    uint4* w1q = (uint4*)(sm + SO_W1Q);
    uint4* w2q = (uint4*)(sm + SO_W2Q);
    uint32_t* h1h = (uint32_t*)(sm + SO_H1H);
    uint32_t* h1l = (uint32_t*)(sm + SO_H1L);
    float* b1s = (float*)(sm + SO_B1);
    float* b2s = (float*)(sm + SO_B2);
    float* w3s = (float*)(sm + SO_W3);
    float* scl = (float*)(sm + SO_SC);
    float* pb0 = (float*)(sm + SO_PB0);
    float* pb1 = (float*)(sm + SO_PB1);

    if (blockIdx.x == 0 && tid == 0) { g_max_out_i = 0; g_max_enh_i = 0; }

    // ---- stage biases / w3 row 2 / scalars ----
    if (tid < 128) b1s[tid] = b1[tid];
    else if (tid < 192) b2s[tid - 128] = b2[tid - 128];
    else if (tid < 256) w3s[tid - 192] = W3[2 * H2_ + (tid - 192)];
    if (tid == 0) { scl[0] = *a1p; scl[1] = *a2p; scl[2] = b3[2]; }

    // ---- stage W1 -> interleaved hi/lo granules (1024 threads) ----
    {
        const int row = tid >> 3;          // 0..127
        const int q   = tid & 7;           // 2 kt each
        const float* src = W1 + (size_t)row * GRUH;
        #pragma unroll
        for (int kk = 0; kk < 2; ++kk) {
            const int kt = q * 2 + kk;
            const float4* s4 = (const float4*)(src + kt * 16);
            float4 f0 = s4[0], f1 = s4[1], f2 = s4[2], f3 = s4[3];
            uint32_t h[8], l[8];
            split2(f0.x, f0.y, h[0], l[0]); split2(f0.z, f0.w, h[1], l[1]);
            split2(f1.x, f1.y, h[2], l[2]); split2(f1.z, f1.w, h[3], l[3]);
            split2(f2.x, f2.y, h[4], l[4]); split2(f2.z, f2.w, h[5], l[5]);
            split2(f3.x, f3.y, h[6], l[6]); split2(f3.z, f3.w, h[7], l[7]);
            uint4* g = w1q + row * W1_GSTRIDE + kt * 4;
            #pragma unroll
            for (int t = 0; t < 4; ++t)
                g[t] = make_uint4(h[t], h[t + 4], l[t], l[t + 4]);
        }
    }
    // ---- stage W2 (threads 0..511) ----
    if (tid < 512) {
        const int row = tid >> 3;          // 0..63
        const int kt  = tid & 7;           // 0..7
        const float4* s4 = (const float4*)(W2 + (size_t)row * H1_ + kt * 16);
        float4 f0 = s4[0], f1 = s4[1], f2 = s4[2], f3 = s4[3];
        uint32_t h[8], l[8];
        split2(f0.x, f0.y, h[0], l[0]); split2(f0.z, f0.w, h[1], l[1]);
        split2(f1.x, f1.y, h[2], l[2]); split2(f1.z, f1.w, h[3], l[3]);
        split2(f2.x, f2.y, h[4], l[4]); split2(f2.z, f2.w, h[5], l[5]);
        split2(f3.x, f3.y, h[6], l[6]); split2(f3.z, f3.w, h[7], l[7]);
        uint4* g = w2q + row * W2_GSTRIDE + kt * 4;
        #pragma unroll
        for (int t = 0; t < 4; ++t)
            g[t] = make_uint4(h[t], h[t + 4], l[t], l[t + 4]);
    }
    __syncthreads();

    // ========= GEMM1: [256 x 256] * W1^T -> [256 x 128] =========
    // warp = (wid_m 0..15, nhalf 0..1): rows wid_m*16 + {grp, grp+8},
    // cols nhalf*64 .. +64
    const int wid_m  = wid >> 1;
    const int nhalf  = wid & 1;
    const float* xr0 = X + (size_t)(m0 + wid_m * 16 + grp) * GRUH;
    const float* xr8 = xr0 + 8 * GRUH;

    float acc[8][4];
    #pragma unroll
    for (int nt = 0; nt < 8; ++nt)
        #pragma unroll
        for (int j = 0; j < 4; ++j) acc[nt][j] = 0.0f;

    float2 c00, c10, c01, c11;
    {
        const int k0 = tig * 2;
        c00 = *(const float2*)(xr0 + k0);  c01 = *(const float2*)(xr0 + k0 + 8);
        c10 = *(const float2*)(xr8 + k0);  c11 = *(const float2*)(xr8 + k0 + 8);
    }

    #pragma unroll 1
    for (int kt = 0; kt < 16; ++kt) {
        uint32_t ah[4], al[4];
        split2(c00.x, c00.y, ah[0], al[0]);
        split2(c10.x, c10.y, ah[1], al[1]);
        split2(c01.x, c01.y, ah[2], al[2]);
        split2(c11.x, c11.y, ah[3], al[3]);

        // prefetch next kt
        {
            const int ktn = (kt < 15) ? kt + 1 : 15;
            const int k0 = ktn * 16 + tig * 2;
            c00 = *(const float2*)(xr0 + k0);  c01 = *(const float2*)(xr0 + k0 + 8);
            c10 = *(const float2*)(xr8 + k0);  c11 = *(const float2*)(xr8 + k0 + 8);
        }

        const uint4* p = w1q + (nhalf * 64 + grp) * W1_GSTRIDE + kt * 4 + tig;
        #pragma unroll
        for (int nt = 0; nt < 8; ++nt) {
            uint4 g = *p;
            p += 8 * W1_GSTRIDE;
            MMA(acc[nt], ah, g.x, g.y);
            MMA(acc[nt], ah, g.z, g.w);
            MMA(acc[nt], al, g.x, g.y);
        }
    }
    __syncthreads();   // all warps finished reading W1 smem

    // ---- epilogue 1: bias + prelu, split hi/lo -> H1 smem (over old W1) ----
    {
        const float A1 = scl[0];
        const int r = wid_m * 16 + grp;
        #pragma unroll
        for (int nt = 0; nt < 8; ++nt) {
            const int col0 = nhalf * 64 + nt * 8 + tig * 2;
            float v00 = acc[nt][0] + b1s[col0];
            float v01 = acc[nt][1] + b1s[col0 + 1];
            float v80 = acc[nt][2] + b1s[col0];
            float v81 = acc[nt][3] + b1s[col0 + 1];
            v00 = (v00 >= 0.0f) ? v00 : A1 * v00;
            v01 = (v01 >= 0.0f) ? v01 : A1 * v01;
            v80 = (v80 >= 0.0f) ? v80 : A1 * v80;
            v81 = (v81 >= 0.0f) ? v81 : A1 * v81;
            uint32_t h0, l0, h8, l8;
            split2(v00, v01, h0, l0);
            split2(v80, v81, h8, l8);
            const int cw = nhalf * 32 + nt * 4 + tig;
            const int w0 = r * H1_WSTRIDE + cw;
            const int w8 = (r + 8) * H1_WSTRIDE + cw;
            h1h[w0] = h0; h1l[w0] = l0;
            h1h[w8] = h8; h1l[w8] = l8;
        }
    }
    __syncthreads();

    // ========= GEMM2: [256 x 128] * W2^T -> [256 x 64] =========
    // warp = (wid_m, nhalf): rows wid_m*16 + {grp, grp+8}, cols nhalf*32..+32
    float acc2[4][4];
    #pragma unroll
    for (int nt = 0; nt < 4; ++nt)
        #pragma unroll
        for (int j = 0; j < 4; ++j) acc2[nt][j] = 0.0f;

    const int r0w = (wid_m * 16 + grp) * H1_WSTRIDE;
    const int r8w = (wid_m * 16 + grp + 8) * H1_WSTRIDE;

    #pragma unroll 1
    for (int kt = 0; kt < 8; ++kt) {
        const int wbase = kt * 8 + tig;
        uint32_t ah[4], al[4];
        ah[0] = h1h[r0w + wbase];     al[0] = h1l[r0w + wbase];
        ah[1] = h1h[r8w + wbase];     al[1] = h1l[r8w + wbase];
        ah[2] = h1h[r0w + wbase + 4]; al[2] = h1l[r0w + wbase + 4];
        ah[3] = h1h[r8w + wbase + 4]; al[3] = h1l[r8w + wbase + 4];
        const uint4* p = w2q + (nhalf * 32 + grp) * W2_GSTRIDE + kt * 4 + tig;
        #pragma unroll
        for (int nt = 0; nt < 4; ++nt) {
            uint4 g = *p;
            p += 8 * W2_GSTRIDE;
            MMA(acc2[nt], ah, g.x, g.y);
            MMA(acc2[nt], ah, g.z, g.w);
            MMA(acc2[nt], al, g.x, g.y);
        }
    }

    // ---- epilogue 2: bias + prelu, partial w3 dot, pair-reduce in smem ----
    {
        const float A2 = scl[1];
        float p0 = 0.0f, p8 = 0.0f;
        #pragma unroll
        for (int nt = 0; nt < 4; ++nt) {
            const int col0 = nhalf * 32 + nt * 8 + tig * 2;
            float v00 = acc2[nt][0] + b2s[col0];
            float v01 = acc2[nt][1] + b2s[col0 + 1];
            float v80 = acc2[nt][2] + b2s[col0];
            float v81 = acc2[nt][3] + b2s[col0 + 1];
            v00 = (v00 >= 0.0f) ? v00 : A2 * v00;
            v01 = (v01 >= 0.0f) ? v01 : A2 * v01;
            v80 = (v80 >= 0.0f) ? v80 : A2 * v80;
            v81 = (v81 >= 0.0f) ? v81 : A2 * v81;
            p0 = fmaf(v00, w3s[col0], fmaf(v01, w3s[col0 + 1], p0));
            p8 = fmaf(v80, w3s[col0], fmaf(v81, w3s[col0 + 1], p8));
        }
        p0 += __shfl_xor_sync(0xffffffffu, p0, 1);
        p0 += __shfl_xor_sync(0xffffffffu, p0, 2);
        p8 += __shfl_xor_sync(0xffffffffu, p8, 1);
        p8 += __shfl_xor_sync(0xffffffffu, p8, 2);
        if (tig == 0) {
            float* pb = nhalf ? pb1 : pb0;
            pb[wid_m * 16 + grp]     = p0;
            pb[wid_m * 16 + grp + 8] = p8;
        }
    }
    __syncthreads();

    // ---- finalize: softplus over 256 tokens ----
    if (tid < TOK) {
        float p = pb0[tid] + pb1[tid] + scl[2];
        float sp = fmaxf(p, 0.0f) + log1pf(expf(-fabsf(p)));
        float ratio = fminf(fmaxf(sp + 1.0f, 1.0f), 20.0f);
        g_ratio[m0 + tid] = ratio;
    }
}

// =====================================================================
// Kernel B: blocked IIR (8 samples/lane + warp scan per 256 samples)
// =====================================================================
#define CCHUNK 1280
#define CWARM  256
#define C_PB   (N_ / CCHUNK)    // 250 chunks per batch

__device__ __forceinline__ float interp_ratio(const float* __restrict__ rb, int n)
{
    float src = ((float)n + 0.5f) * 0.0125f - 0.5f;
    src = fminf(fmaxf(src, 0.0f), 3999.0f);
    float f0 = floorf(src);
    int   i0 = (int)f0;
    int   i1 = min(i0 + 1, 3999);
    float w  = src - f0;
    return rb[i0] * (1.0f - w) + rb[i1] * w;
}
__device__ __forceinline__ float gain_of(float x, float thr, float ratio)
{
    float env = fabsf(x);
    float gr  = (env > thr) ? (thr + __fdividef(env - thr, ratio)) : env;
    float g   = __fdividef(gr, env + 1e-8f);
    return fminf(fmaxf(g, 0.1f), 2.0f);
}

__global__ __launch_bounds__(256)
void compress_kernel(const float* __restrict__ enh,
                     const float* __restrict__ noisy,
                     float* __restrict__ out)
{
    const int w    = (blockIdx.x * blockDim.x + threadIdx.x) >> 5;
    const int lane = threadIdx.x & 31;
    const int b     = w / C_PB;
    const int chunk = w % C_PB;
    const int t0    = chunk * CCHUNK;
    const int start = (chunk == 0) ? 0 : (t0 - CWARM);

    const float* eb = enh   + (size_t)b * N_;
    const float* nb = noisy + (size_t)b * N_;
    float*       ob = out   + (size_t)b * N_;
    const float* rb = g_ratio + b * T_;

    const float q   = 0.43046721f;                    // 0.9^8
    const float qi  = powf(q, (float)lane);           // q^lane
    const float q32 = 1.9342813113834067e-12f;        // 0.9^256

    float s_in_e, s_in_r;
    {
        float e  = eb[start];
        float nn = nb[start];
        float ratio = interp_ratio(rb, start);
        s_in_e = gain_of(e, 0.3f, ratio);
        s_in_r = gain_of(nn - e, 0.1f, ratio * 0.5f);
    }

    float mx_out = 0.0f, mx_enh = 0.0f;
    const int nend = t0 + CCHUNK;

    #pragma unroll 1
    for (int g0 = start; g0 < nend; g0 += 256) {
        const int n0 = g0 + lane * 8;
        float4 e0 = *(const float4*)(eb + n0);
        float4 e1 = *(const float4*)(eb + n0 + 4);
        float4 x0 = *(const float4*)(nb + n0);
        float4 x1 = *(const float4*)(nb + n0 + 4);
        float e[8] = {e0.x, e0.y, e0.z, e0.w, e1.x, e1.y, e1.z, e1.w};
        float x[8] = {x0.x, x0.y, x0.z, x0.w, x1.x, x1.y, x1.z, x1.w};

        float r[8], le[8], lr[8];
        float se = 0.0f, sr = 0.0f;
        #pragma unroll
        for (int j = 0; j < 8; ++j) {
            r[j] = x[j] - e[j];
            float ratio = interp_ratio(rb, n0 + j);
            float ge = gain_of(e[j], 0.3f, ratio);
            float gr = gain_of(r[j], 0.1f, ratio * 0.5f);
            se = fmaf(0.9f, se, 0.1f * ge);  le[j] = se;
            sr = fmaf(0.9f, sr, 0.1f * gr);  lr[j] = sr;
        }

        float Ie = se, Ir = sr, t;
        t = __shfl_up_sync(0xffffffffu, Ie, 1);  if (lane >= 1)  Ie = fmaf(0.43046721f,            t, Ie);
        t = __shfl_up_sync(0xffffffffu, Ir, 1);  if (lane >= 1)  Ir = fmaf(0.43046721f,            t, Ir);
        t = __shfl_up_sync(0xffffffffu, Ie, 2);  if (lane >= 2)  Ie = fmaf(0.1853020188851841f,    t, Ie);
        t = __shfl_up_sync(0xffffffffu, Ir, 2);  if (lane >= 2)  Ir = fmaf(0.1853020188851841f,    t, Ir);
        t = __shfl_up_sync(0xffffffffu, Ie, 4);  if (lane >= 4)  Ie = fmaf(0.03433683820292512f,   t, Ie);
        t = __shfl_up_sync(0xffffffffu, Ir, 4);  if (lane >= 4)  Ir = fmaf(0.03433683820292512f,   t, Ir);
        t = __shfl_up_sync(0xffffffffu, Ie, 8);  if (lane >= 8)  Ie = fmaf(0.001179018457773862f,  t, Ie);
        t = __shfl_up_sync(0xffffffffu, Ir, 8);  if (lane >= 8)  Ir = fmaf(0.001179018457773862f,  t, Ir);
        t = __shfl_up_sync(0xffffffffu, Ie, 16); if (lane >= 16) Ie = fmaf(1.390084523771456e-06f, t, Ie);
        t = __shfl_up_sync(0xffffffffu, Ir, 16); if (lane >= 16) Ir = fmaf(1.390084523771456e-06f, t, Ir);

        float ce = __shfl_up_sync(0xffffffffu, Ie, 1); if (lane == 0) ce = 0.0f;
        float cr = __shfl_up_sync(0xffffffffu, Ir, 1); if (lane == 0) cr = 0.0f;
        ce = fmaf(qi, s_in_e, ce);
        cr = fmaf(qi, s_in_r, cr);

        float Ie31 = __shfl_sync(0xffffffffu, Ie, 31);
        float Ir31 = __shfl_sync(0xffffffffu, Ir, 31);
        s_in_e = fmaf(q32, s_in_e, Ie31);
        s_in_r = fmaf(q32, s_in_r, Ir31);

        if (g0 >= t0) {
            const float d[8] = {0.9f, 0.81f, 0.729f, 0.6561f,
                                0.59049f, 0.531441f, 0.4782969f, 0.43046721f};
            float o[8];
            #pragma unroll
            for (int j = 0; j < 8; ++j) {
                float sej = fmaf(d[j], ce, le[j]);
                float srj = fmaf(d[j], cr, lr[j]);
                o[j] = fmaf(sej, e[j], 0.1f * (srj * r[j]));
                mx_out = fmaxf(mx_out, fabsf(o[j]));
                mx_enh = fmaxf(mx_enh, fabsf(e[j]));
            }
            *(float4*)(ob + n0)     = make_float4(o[0], o[1], o[2], o[3]);
            *(float4*)(ob + n0 + 4) = make_float4(o[4], o[5], o[6], o[7]);
        }
    }

    #pragma unroll
    for (int off = 16; off > 0; off >>= 1) {
        mx_out = fmaxf(mx_out, __shfl_xor_sync(0xffffffffu, mx_out, off));
        mx_enh = fmaxf(mx_enh, __shfl_xor_sync(0xffffffffu, mx_enh, off));
    }
    if (lane == 0) {
        atomicMax(&g_max_out_i, __float_as_int(mx_out));
        atomicMax(&g_max_enh_i, __float_as_int(mx_enh));
    }
}

// =====================================================================
// Kernel C: normalize
// =====================================================================
__global__ __launch_bounds__(256)
void scale_kernel(float* __restrict__ out)
{
    const float mo = __int_as_float(g_max_out_i);
    const float me = __int_as_float(g_max_enh_i);
    const float s  = me / (mo + 1e-8f);
    const int i = blockIdx.x * blockDim.x + threadIdx.x;
    const int n4 = (B_ * N_) / 4;
    if (i < n4) {
        float4* o4 = (float4*)out;
        float4 v = o4[i];
        v.x *= s; v.y *= s; v.z *= s; v.w *= s;
        o4[i] = v;
    }
}

// =====================================================================
extern "C" void kernel_launch(void* const* d_in, const int* in_sizes, int n_in,
                              void* d_out, int out_size)
{
    const float* gru   = (const float*)d_in[0];
    const float* enh   = (const float*)d_in[1];
    const float* noisy = (const float*)d_in[2];
    const float* W1    = (const float*)d_in[3];
    const float* b1    = (const float*)d_in[4];
    const float* a1    = (const float*)d_in[5];
    const float* W2    = (const float*)d_in[6];
    const float* b2    = (const float*)d_in[7];
    const float* a2    = (const float*)d_in[8];
    const float* W3    = (const float*)d_in[9];
    const float* b3    = (const float*)d_in[10];
    float* out = (float*)d_out;

    cudaFuncSetAttribute(mlp_mma_kernel, cudaFuncAttributeMaxDynamicSharedMemorySize, MLP_SMEM);

    mlp_mma_kernel<<<M_ / TOK, 1024, MLP_SMEM>>>(gru, W1, b1, a1, W2, b2, a2, W3, b3);
    compress_kernel<<<(B_ * C_PB) / 8, 256>>>(enh, noisy, out);
    scale_kernel<<<((B_ * N_ / 4) + 255) / 256, 256>>>(out);
}

// round 11
// speedup vs baseline: 1.1378x; 1.1378x over previous
#include <cuda_runtime.h>
#include <cuda_bf16.h>
#include <math.h>
#include <stdint.h>

// ---------------- problem constants ----------------
#define B_    16
#define T_    4000
#define GRUH  256
#define H1_   128
#define H2_   64
#define N_    320000          // T_ * HOP(80)
#define M_    (B_ * T_)       // 64000 tokens

// ---------------- device scratch ----------------
__device__ float g_ratio[M_];
__device__ int   g_max_out_i;
__device__ int   g_max_enh_i;
__device__ unsigned g_done;
__device__ uint4 g_w1q[128 * 68];   // W1 hi/lo granules (gmem master copy)
__device__ uint4 g_w2q[64 * 36];    // W2 hi/lo granules

// =====================================================================
// helpers
// =====================================================================
__device__ __forceinline__ uint32_t pack_bf16x2(__nv_bfloat16 a, __nv_bfloat16 b) {
    return (uint32_t)__bfloat16_as_ushort(a) | ((uint32_t)__bfloat16_as_ushort(b) << 16);
}
__device__ __forceinline__ void split2(float v0, float v1, uint32_t& hi, uint32_t& lo) {
    __nv_bfloat16 h0 = __float2bfloat16_rn(v0);
    __nv_bfloat16 h1 = __float2bfloat16_rn(v1);
    float l0 = v0 - __bfloat162float(h0);
    float l1 = v1 - __bfloat162float(h1);
    hi = pack_bf16x2(h0, h1);
    lo = pack_bf16x2(__float2bfloat16_rn(l0), __float2bfloat16_rn(l1));
}
// m16n8k16 bf16 MMA, f32 accumulate (portable PTX, sm_80+)
__device__ __forceinline__ void mma_bf16_(float c[4], const uint32_t a[4],
                                          uint32_t b0, uint32_t b1) {
    asm volatile(
        "mma.sync.aligned.m16n8k16.row.col.f32.bf16.bf16.f32 "
        "{%0,%1,%2,%3}, {%4,%5,%6,%7}, {%8,%9}, {%0,%1,%2,%3};"
        : "+f"(c[0]), "+f"(c[1]), "+f"(c[2]), "+f"(c[3])
        : "r"(a[0]), "r"(a[1]), "r"(a[2]), "r"(a[3]), "r"(b0), "r"(b1));
}
#define MMA(c, a, b0, b1) mma_bf16_(c, a, b0, b1)

#define W1_GSTRIDE 68
#define W2_GSTRIDE 36
#define H1_WSTRIDE 68

// =====================================================================
// Kernel P: one-time weight conversion to hi/lo granules + flag reset
//   CTAs 0..3: W1 rows [bid*32, bid*32+32);  CTA 4: W2 + resets.
// =====================================================================
__global__ __launch_bounds__(256)
void prep_kernel(const float* __restrict__ W1, const float* __restrict__ W2)
{
    const int tid = threadIdx.x;
    const int bid = blockIdx.x;
    if (bid < 4) {
        const int row = bid * 32 + (tid >> 3);
        const int q   = tid & 7;
        const float* src = W1 + (size_t)row * GRUH;
        #pragma unroll
        for (int kk = 0; kk < 2; ++kk) {
            const int kt = q * 2 + kk;
            const float4* s4 = (const float4*)(src + kt * 16);
            float4 f0 = s4[0], f1 = s4[1], f2 = s4[2], f3 = s4[3];
            uint32_t h[8], l[8];
            split2(f0.x, f0.y, h[0], l[0]); split2(f0.z, f0.w, h[1], l[1]);
            split2(f1.x, f1.y, h[2], l[2]); split2(f1.z, f1.w, h[3], l[3]);
            split2(f2.x, f2.y, h[4], l[4]); split2(f2.z, f2.w, h[5], l[5]);
            split2(f3.x, f3.y, h[6], l[6]); split2(f3.z, f3.w, h[7], l[7]);
            uint4* g = g_w1q + row * W1_GSTRIDE + kt * 4;
            #pragma unroll
            for (int t = 0; t < 4; ++t)
                g[t] = make_uint4(h[t], h[t + 4], l[t], l[t + 4]);
        }
    } else {
        if (tid == 0) { g_done = 0u; g_max_out_i = 0; g_max_enh_i = 0; }
        const int row = tid >> 2;          // 0..63
        const int q   = tid & 3;
        const float* src = W2 + (size_t)row * H1_;
        #pragma unroll
        for (int kk = 0; kk < 2; ++kk) {
            const int kt = q * 2 + kk;
            const float4* s4 = (const float4*)(src + kt * 16);
            float4 f0 = s4[0], f1 = s4[1], f2 = s4[2], f3 = s4[3];
            uint32_t h[8], l[8];
            split2(f0.x, f0.y, h[0], l[0]); split2(f0.z, f0.w, h[1], l[1]);
            split2(f1.x, f1.y, h[2], l[2]); split2(f1.z, f1.w, h[3], l[3]);
            split2(f2.x, f2.y, h[4], l[4]); split2(f2.z, f2.w, h[5], l[5]);
            split2(f3.x, f3.y, h[6], l[6]); split2(f3.z, f3.w, h[7], l[7]);
            uint4* g = g_w2q + row * W2_GSTRIDE + kt * 4;
            #pragma unroll
            for (int t = 0; t < 4; ++t)
                g[t] = make_uint4(h[t], h[t + 4], l[t], l[t + 4]);
        }
    }
}

// =====================================================================
// Kernel A: fused split-bf16 MLP via mma.sync  ->  ratio[m]
//   256 tokens/CTA, 250 CTAs, 512 threads (R6/R7 proven mapping);
//   weights copied from pre-converted gmem granules (no per-CTA math).
// =====================================================================
#define TOK 256

#define SO_W2Q  0
#define SO_B1   36864
#define SO_B2   37376
#define SO_W3   37632
#define SO_SC   37888
#define SO_W1Q  38016
#define SO_H1H  38016
#define SO_H1L  107648
#define MLP_SMEM 177280

__global__ __launch_bounds__(512, 1)
void mlp_mma_kernel(const float* __restrict__ X,
                    const float* __restrict__ b1, const float* __restrict__ a1p,
                    const float* __restrict__ b2, const float* __restrict__ a2p,
                    const float* __restrict__ W3, const float* __restrict__ b3)
{
    extern __shared__ char sm[];
    const int tid  = threadIdx.x;
    const int wid  = tid >> 5;
    const int lane = tid & 31;
    const int grp  = lane >> 2;
    const int tig  = lane & 3;
    const int m0   = blockIdx.x * TOK;

    uint4* w1q = (uint4*)(sm + SO_W1Q);
    uint4* w2q = (uint4*)(sm + SO_W2Q);
    uint32_t* h1h = (uint32_t*)(sm + SO_H1H);
    uint32_t* h1l = (uint32_t*)(sm + SO_H1L);
    float* b1s = (float*)(sm + SO_B1);
    float* b2s = (float*)(sm + SO_B2);
    float* w3s = (float*)(sm + SO_W3);
    float* scl = (float*)(sm + SO_SC);

    // ---- stage biases / w3 row 2 / scalars ----
    if (tid < 128) b1s[tid] = b1[tid];
    else if (tid < 192) b2s[tid - 128] = b2[tid - 128];
    else if (tid < 256) w3s[tid - 192] = W3[2 * H2_ + (tid - 192)];
    if (tid == 0) { scl[0] = *a1p; scl[1] = *a2p; scl[2] = b3[2]; }

    // ---- copy pre-converted weight granules into smem ----
    #pragma unroll 4
    for (int i = tid; i < 128 * W1_GSTRIDE; i += 512) w1q[i] = g_w1q[i];
    #pragma unroll 2
    for (int i = tid; i < 64 * W2_GSTRIDE; i += 512) w2q[i] = g_w2q[i];
    __syncthreads();

    // ========= GEMM1: [256 x 256] * W1^T -> [256 x 128] =========
    const int wid_m  = wid >> 1;
    const int nhalf  = wid & 1;
    const float* xr0  = X + (size_t)(m0 + wid_m * 32 + grp) * GRUH;
    const float* xr8  = xr0 + 8  * GRUH;
    const float* xr16 = xr0 + 16 * GRUH;
    const float* xr24 = xr0 + 24 * GRUH;

    float acc[2][8][4];
    #pragma unroll
    for (int t = 0; t < 2; ++t)
        #pragma unroll
        for (int nt = 0; nt < 8; ++nt)
            #pragma unroll
            for (int j = 0; j < 4; ++j) acc[t][nt][j] = 0.0f;

    float2 c00, c10, c20, c30, c01, c11, c21, c31;
    {
        const int k0 = tig * 2;
        c00 = *(const float2*)(xr0  + k0);  c01 = *(const float2*)(xr0  + k0 + 8);
        c10 = *(const float2*)(xr8  + k0);  c11 = *(const float2*)(xr8  + k0 + 8);
        c20 = *(const float2*)(xr16 + k0);  c21 = *(const float2*)(xr16 + k0 + 8);
        c30 = *(const float2*)(xr24 + k0);  c31 = *(const float2*)(xr24 + k0 + 8);
    }

    #pragma unroll 1
    for (int kt = 0; kt < 16; ++kt) {
        uint32_t ah0[4], al0[4], ah1[4], al1[4];
        split2(c00.x, c00.y, ah0[0], al0[0]);
        split2(c10.x, c10.y, ah0[1], al0[1]);
        split2(c01.x, c01.y, ah0[2], al0[2]);
        split2(c11.x, c11.y, ah0[3], al0[3]);
        split2(c20.x, c20.y, ah1[0], al1[0]);
        split2(c30.x, c30.y, ah1[1], al1[1]);
        split2(c21.x, c21.y, ah1[2], al1[2]);
        split2(c31.x, c31.y, ah1[3], al1[3]);

        {
            const int ktn = (kt < 15) ? kt + 1 : 15;
            const int k0 = ktn * 16 + tig * 2;
            c00 = *(const float2*)(xr0  + k0);  c01 = *(const float2*)(xr0  + k0 + 8);
            c10 = *(const float2*)(xr8  + k0);  c11 = *(const float2*)(xr8  + k0 + 8);
            c20 = *(const float2*)(xr16 + k0);  c21 = *(const float2*)(xr16 + k0 + 8);
            c30 = *(const float2*)(xr24 + k0);  c31 = *(const float2*)(xr24 + k0 + 8);
        }

        const uint4* p = w1q + (nhalf * 64 + grp) * W1_GSTRIDE + kt * 4 + tig;
        #pragma unroll
        for (int nt = 0; nt < 8; ++nt) {
            uint4 g = *p;
            p += 8 * W1_GSTRIDE;
            MMA(acc[0][nt], ah0, g.x, g.y);
            MMA(acc[0][nt], ah0, g.z, g.w);
            MMA(acc[0][nt], al0, g.x, g.y);
            MMA(acc[1][nt], ah1, g.x, g.y);
            MMA(acc[1][nt], ah1, g.z, g.w);
            MMA(acc[1][nt], al1, g.x, g.y);
        }
    }
    __syncthreads();

    // ---- epilogue 1: bias + prelu, split hi/lo -> H1 smem ----
    {
        const float A1 = scl[0];
        const int rbase = wid_m * 32 + grp;
        #pragma unroll
        for (int t = 0; t < 2; ++t) {
            const int r = rbase + t * 16;
            #pragma unroll
            for (int nt = 0; nt < 8; ++nt) {
                const int col0 = nhalf * 64 + nt * 8 + tig * 2;
                float v00 = acc[t][nt][0] + b1s[col0];
                float v01 = acc[t][nt][1] + b1s[col0 + 1];
                float v80 = acc[t][nt][2] + b1s[col0];
                float v81 = acc[t][nt][3] + b1s[col0 + 1];
                v00 = (v00 >= 0.0f) ? v00 : A1 * v00;
                v01 = (v01 >= 0.0f) ? v01 : A1 * v01;
                v80 = (v80 >= 0.0f) ? v80 : A1 * v80;
                v81 = (v81 >= 0.0f) ? v81 : A1 * v81;
                uint32_t h0, l0, h8, l8;
                split2(v00, v01, h0, l0);
                split2(v80, v81, h8, l8);
                const int cw = nhalf * 32 + nt * 4 + tig;
                const int w0 = r * H1_WSTRIDE + cw;
                const int w8 = (r + 8) * H1_WSTRIDE + cw;
                h1h[w0] = h0; h1l[w0] = l0;
                h1h[w8] = h8; h1l[w8] = l8;
            }
        }
    }
    __syncthreads();

    // ========= GEMM2: [256 x 128] * W2^T -> [256 x 64] =========
    float acc2[8][4];
    #pragma unroll
    for (int nt = 0; nt < 8; ++nt)
        #pragma unroll
        for (int j = 0; j < 4; ++j) acc2[nt][j] = 0.0f;

    const int r0w = (wid * 16 + grp) * H1_WSTRIDE;
    const int r8w = (wid * 16 + grp + 8) * H1_WSTRIDE;

    #pragma unroll 1
    for (int kt = 0; kt < 8; ++kt) {
        const int wbase = kt * 8 + tig;
        uint32_t ah[4], al[4];
        ah[0] = h1h[r0w + wbase];     al[0] = h1l[r0w + wbase];
        ah[1] = h1h[r8w + wbase];     al[1] = h1l[r8w + wbase];
        ah[2] = h1h[r0w + wbase + 4]; al[2] = h1l[r0w + wbase + 4];
        ah[3] = h1h[r8w + wbase + 4]; al[3] = h1l[r8w + wbase + 4];
        const uint4* p = w2q + grp * W2_GSTRIDE + kt * 4 + tig;
        #pragma unroll
        for (int nt = 0; nt < 8; ++nt) {
            uint4 g = *p;
            p += 8 * W2_GSTRIDE;
            MMA(acc2[nt], ah, g.x, g.y);
            MMA(acc2[nt], ah, g.z, g.w);
            MMA(acc2[nt], al, g.x, g.y);
        }
    }

    // ---- epilogue 2: bias + prelu, dot w3, reduce over tig, softplus ----
    {
        const float A2 = scl[1];
        float p0 = 0.0f, p8 = 0.0f;
        #pragma unroll
        for (int nt = 0; nt < 8; ++nt) {
            const int col0 = nt * 8 + tig * 2;
            float v00 = acc2[nt][0] + b2s[col0];
            float v01 = acc2[nt][1] + b2s[col0 + 1];
            float v80 = acc2[nt][2] + b2s[col0];
            float v81 = acc2[nt][3] + b2s[col0 + 1];
            v00 = (v00 >= 0.0f) ? v00 : A2 * v00;
            v01 = (v01 >= 0.0f) ? v01 : A2 * v01;
            v80 = (v80 >= 0.0f) ? v80 : A2 * v80;
            v81 = (v81 >= 0.0f) ? v81 : A2 * v81;
            p0 = fmaf(v00, w3s[col0], fmaf(v01, w3s[col0 + 1], p0));
            p8 = fmaf(v80, w3s[col0], fmaf(v81, w3s[col0 + 1], p8));
        }
        p0 += __shfl_xor_sync(0xffffffffu, p0, 1);
        p0 += __shfl_xor_sync(0xffffffffu, p0, 2);
        p8 += __shfl_xor_sync(0xffffffffu, p8, 1);
        p8 += __shfl_xor_sync(0xffffffffu, p8, 2);
        if (tig == 0) {
            const float bb3 = scl[2];
            float pa = p0 + bb3;
            float pb = p8 + bb3;
            float spa = fmaxf(pa, 0.0f) + log1pf(expf(-fabsf(pa)));
            float spb = fmaxf(pb, 0.0f) + log1pf(expf(-fabsf(pb)));
            float ra = fminf(fmaxf(spa + 1.0f, 1.0f), 20.0f);
            float rb = fminf(fmaxf(spb + 1.0f, 1.0f), 20.0f);
            g_ratio[m0 + wid * 16 + grp]     = ra;
            g_ratio[m0 + wid * 16 + grp + 8] = rb;
        }
    }
}

// =====================================================================
// Kernel B: blocked IIR + fused device-wide normalize.
//   500 CTAs; __launch_bounds__(256,4) caps regs at 64 so >=4 CTAs/SM
//   are resident (592 slots >= 500) -> arrive/spin barrier is safe.
// =====================================================================
#define CCHUNK 1280
#define CWARM  256
#define C_PB   (N_ / CCHUNK)    // 250 chunks per batch
#define CGRID  ((B_ * C_PB) / 8)  // 500 CTAs

__device__ __forceinline__ float interp_ratio(const float* __restrict__ rb, int n)
{
    float src = ((float)n + 0.5f) * 0.0125f - 0.5f;
    src = fminf(fmaxf(src, 0.0f), 3999.0f);
    float f0 = floorf(src);
    int   i0 = (int)f0;
    int   i1 = min(i0 + 1, 3999);
    float w  = src - f0;
    return rb[i0] * (1.0f - w) + rb[i1] * w;
}
__device__ __forceinline__ float gain_of(float x, float thr, float ratio)
{
    float env = fabsf(x);
    float gr  = (env > thr) ? (thr + __fdividef(env - thr, ratio)) : env;
    float g   = __fdividef(gr, env + 1e-8f);
    return fminf(fmaxf(g, 0.1f), 2.0f);
}

__global__ __launch_bounds__(256, 4)
void compress_kernel(const float* __restrict__ enh,
                     const float* __restrict__ noisy,
                     float* __restrict__ out)
{
    const int w    = (blockIdx.x * blockDim.x + threadIdx.x) >> 5;
    const int lane = threadIdx.x & 31;
    const int b     = w / C_PB;
    const int chunk = w % C_PB;
    const int t0    = chunk * CCHUNK;
    const int start = (chunk == 0) ? 0 : (t0 - CWARM);

    const float* eb = enh   + (size_t)b * N_;
    const float* nb = noisy + (size_t)b * N_;
    float*       ob = out   + (size_t)b * N_;
    const float* rb = g_ratio + b * T_;

    const float q   = 0.43046721f;                    // 0.9^8
    const float qi  = powf(q, (float)lane);
    const float q32 = 1.9342813113834067e-12f;        // 0.9^256

    float s_in_e, s_in_r;
    {
        float e  = eb[start];
        float nn = nb[start];
        float ratio = interp_ratio(rb, start);
        s_in_e = gain_of(e, 0.3f, ratio);
        s_in_r = gain_of(nn - e, 0.1f, ratio * 0.5f);
    }

    float mx_out = 0.0f, mx_enh = 0.0f;
    const int nend = t0 + CCHUNK;

    #pragma unroll 1
    for (int g0 = start; g0 < nend; g0 += 256) {
        const int n0 = g0 + lane * 8;
        float4 e0 = *(const float4*)(eb + n0);
        float4 e1 = *(const float4*)(eb + n0 + 4);
        float4 x0 = *(const float4*)(nb + n0);
        float4 x1 = *(const float4*)(nb + n0 + 4);
        float e[8] = {e0.x, e0.y, e0.z, e0.w, e1.x, e1.y, e1.z, e1.w};
        float x[8] = {x0.x, x0.y, x0.z, x0.w, x1.x, x1.y, x1.z, x1.w};

        float r[8], le[8], lr[8];
        float se = 0.0f, sr = 0.0f;
        #pragma unroll
        for (int j = 0; j < 8; ++j) {
            r[j] = x[j] - e[j];
            float ratio = interp_ratio(rb, n0 + j);
            float ge = gain_of(e[j], 0.3f, ratio);
            float gr = gain_of(r[j], 0.1f, ratio * 0.5f);
            se = fmaf(0.9f, se, 0.1f * ge);  le[j] = se;
            sr = fmaf(0.9f, sr, 0.1f * gr);  lr[j] = sr;
        }

        float Ie = se, Ir = sr, t;
        t = __shfl_up_sync(0xffffffffu, Ie, 1);  if (lane >= 1)  Ie = fmaf(0.43046721f,            t, Ie);
        t = __shfl_up_sync(0xffffffffu, Ir, 1);  if (lane >= 1)  Ir = fmaf(0.43046721f,            t, Ir);
        t = __shfl_up_sync(0xffffffffu, Ie, 2);  if (lane >= 2)  Ie = fmaf(0.1853020188851841f,    t, Ie);
        t = __shfl_up_sync(0xffffffffu, Ir, 2);  if (lane >= 2)  Ir = fmaf(0.1853020188851841f,    t, Ir);
        t = __shfl_up_sync(0xffffffffu, Ie, 4);  if (lane >= 4)  Ie = fmaf(0.03433683820292512f,   t, Ie);
        t = __shfl_up_sync(0xffffffffu, Ir, 4);  if (lane >= 4)  Ir = fmaf(0.03433683820292512f,   t, Ir);
        t = __shfl_up_sync(0xffffffffu, Ie, 8);  if (lane >= 8)  Ie = fmaf(0.001179018457773862f,  t, Ie);
        t = __shfl_up_sync(0xffffffffu, Ir, 8);  if (lane >= 8)  Ir = fmaf(0.001179018457773862f,  t, Ir);
        t = __shfl_up_sync(0xffffffffu, Ie, 16); if (lane >= 16) Ie = fmaf(1.390084523771456e-06f, t, Ie);
        t = __shfl_up_sync(0xffffffffu, Ir, 16); if (lane >= 16) Ir = fmaf(1.390084523771456e-06f, t, Ir);

        float ce = __shfl_up_sync(0xffffffffu, Ie, 1); if (lane == 0) ce = 0.0f;
        float cr = __shfl_up_sync(0xffffffffu, Ir, 1); if (lane == 0) cr = 0.0f;
        ce = fmaf(qi, s_in_e, ce);
        cr = fmaf(qi, s_in_r, cr);

        float Ie31 = __shfl_sync(0xffffffffu, Ie, 31);
        float Ir31 = __shfl_sync(0xffffffffu, Ir, 31);
        s_in_e = fmaf(q32, s_in_e, Ie31);
        s_in_r = fmaf(q32, s_in_r, Ir31);

        if (g0 >= t0) {
            const float d[8] = {0.9f, 0.81f, 0.729f, 0.6561f,
                                0.59049f, 0.531441f, 0.4782969f, 0.43046721f};
            float o[8];
            #pragma unroll
            for (int j = 0; j < 8; ++j) {
                float sej = fmaf(d[j], ce, le[j]);
                float srj = fmaf(d[j], cr, lr[j]);
                o[j] = fmaf(sej, e[j], 0.1f * (srj * r[j]));
                mx_out = fmaxf(mx_out, fabsf(o[j]));
                mx_enh = fmaxf(mx_enh, fabsf(e[j]));
            }
            *(float4*)(ob + n0)     = make_float4(o[0], o[1], o[2], o[3]);
            *(float4*)(ob + n0 + 4) = make_float4(o[4], o[5], o[6], o[7]);
        }
    }

    #pragma unroll
    for (int off = 16; off > 0; off >>= 1) {
        mx_out = fmaxf(mx_out, __shfl_xor_sync(0xffffffffu, mx_out, off));
        mx_enh = fmaxf(mx_enh, __shfl_xor_sync(0xffffffffu, mx_enh, off));
    }
    if (lane == 0) {
        atomicMax(&g_max_out_i, __float_as_int(mx_out));
        atomicMax(&g_max_enh_i, __float_as_int(mx_enh));
    }

    // ---- device-wide arrive + spin barrier (all 500 CTAs resident) ----
    __syncthreads();
    if (threadIdx.x == 0) {
        __threadfence();
        atomicAdd(&g_done, 1u);
        while (*(volatile unsigned*)&g_done < (unsigned)gridDim.x)
            __nanosleep(64);
    }
    __syncthreads();
    __threadfence();

    // ---- fused normalize: rescale this warp's own chunk (L2-hot) ----
    {
        const float mo = __int_as_float(*(volatile int*)&g_max_out_i);
        const float me = __int_as_float(*(volatile int*)&g_max_enh_i);
        const float s  = __fdividef(me, mo + 1e-8f);
        #pragma unroll 1
        for (int g0 = t0; g0 < nend; g0 += 256) {
            const int n0 = g0 + lane * 8;
            float4 v0 = *(float4*)(ob + n0);
            float4 v1 = *(float4*)(ob + n0 + 4);
            v0.x *= s; v0.y *= s; v0.z *= s; v0.w *= s;
            v1.x *= s; v1.y *= s; v1.z *= s; v1.w *= s;
            *(float4*)(ob + n0)     = v0;
            *(float4*)(ob + n0 + 4) = v1;
        }
    }
}

// =====================================================================
extern "C" void kernel_launch(void* const* d_in, const int* in_sizes, int n_in,
                              void* d_out, int out_size)
{
    const float* gru   = (const float*)d_in[0];
    const float* enh   = (const float*)d_in[1];
    const float* noisy = (const float*)d_in[2];
    const float* W1    = (const float*)d_in[3];
    const float* b1    = (const float*)d_in[4];
    const float* a1    = (const float*)d_in[5];
    const float* W2    = (const float*)d_in[6];
    const float* b2    = (const float*)d_in[7];
    const float* a2    = (const float*)d_in[8];
    const float* W3    = (const float*)d_in[9];
    const float* b3    = (const float*)d_in[10];
    float* out = (float*)d_out;

    cudaFuncSetAttribute(mlp_mma_kernel, cudaFuncAttributeMaxDynamicSharedMemorySize, MLP_SMEM);

    prep_kernel<<<5, 256>>>(W1, W2);
    mlp_mma_kernel<<<M_ / TOK, 512, MLP_SMEM>>>(gru, b1, a1, b2, a2, W3, b3);
    compress_kernel<<<CGRID, 256>>>(enh, noisy, out);
}

// round 12
// speedup vs baseline: 1.1635x; 1.0226x over previous
#include <cuda_runtime.h>
#include <cuda_bf16.h>
#include <math.h>
#include <stdint.h>

// ---------------- problem constants ----------------
#define B_    16
#define T_    4000
#define GRUH  256
#define H1_   128
#define H2_   64
#define N_    320000          // T_ * HOP(80)
#define M_    (B_ * T_)       // 64000 tokens

// ---------------- device scratch ----------------
__device__ float g_ratio[M_];
__device__ int   g_max_out_i;
__device__ int   g_max_enh_i;
__device__ unsigned g_done;
__device__ uint4 g_w1q[128 * 68];   // W1 hi/lo granules (gmem master copy)
__device__ uint4 g_w2q[64 * 36];    // W2 hi/lo granules

// =====================================================================
// helpers
// =====================================================================
__device__ __forceinline__ uint32_t pack_bf16x2(__nv_bfloat16 a, __nv_bfloat16 b) {
    return (uint32_t)__bfloat16_as_ushort(a) | ((uint32_t)__bfloat16_as_ushort(b) << 16);
}
__device__ __forceinline__ void split2(float v0, float v1, uint32_t& hi, uint32_t& lo) {
    __nv_bfloat16 h0 = __float2bfloat16_rn(v0);
    __nv_bfloat16 h1 = __float2bfloat16_rn(v1);
    float l0 = v0 - __bfloat162float(h0);
    float l1 = v1 - __bfloat162float(h1);
    hi = pack_bf16x2(h0, h1);
    lo = pack_bf16x2(__float2bfloat16_rn(l0), __float2bfloat16_rn(l1));
}
// m16n8k16 bf16 MMA, f32 accumulate (portable PTX, sm_80+)
__device__ __forceinline__ void mma_bf16_(float c[4], const uint32_t a[4],
                                          uint32_t b0, uint32_t b1) {
    asm volatile(
        "mma.sync.aligned.m16n8k16.row.col.f32.bf16.bf16.f32 "
        "{%0,%1,%2,%3}, {%4,%5,%6,%7}, {%8,%9}, {%0,%1,%2,%3};"
        : "+f"(c[0]), "+f"(c[1]), "+f"(c[2]), "+f"(c[3])
        : "r"(a[0]), "r"(a[1]), "r"(a[2]), "r"(a[3]), "r"(b0), "r"(b1));
}
#define MMA(c, a, b0, b1) mma_bf16_(c, a, b0, b1)

#define W1_GSTRIDE 68
#define W2_GSTRIDE 36
#define H1_WSTRIDE 68

// =====================================================================
// Kernel P: one-time weight conversion — 40 CTAs, one granule/thread
// =====================================================================
__global__ __launch_bounds__(256)
void prep_kernel(const float* __restrict__ W1, const float* __restrict__ W2)
{
    const int tid = threadIdx.x;
    const int bid = blockIdx.x;
    if (bid < 32) {
        const int gid = bid * 256 + tid;       // 0..8191
        const int row = gid >> 6;              // 0..127
        const int pos = gid & 63;
        const int kt = pos >> 2, sub = pos & 3;
        const float* src = W1 + (size_t)row * GRUH + kt * 16 + sub * 2;
        float2 fa = *(const float2*)(src);
        float2 fb = *(const float2*)(src + 8);
        uint32_t ha, la, hb, lb;
        split2(fa.x, fa.y, ha, la);
        split2(fb.x, fb.y, hb, lb);
        g_w1q[row * W1_GSTRIDE + kt * 4 + sub] = make_uint4(ha, hb, la, lb);
    } else {
        const int gid = (bid - 32) * 256 + tid; // 0..2047
        const int row = gid >> 5;               // 0..63
        const int pos = gid & 31;
        const int kt = pos >> 2, sub = pos & 3;
        const float* src = W2 + (size_t)row * H1_ + kt * 16 + sub * 2;
        float2 fa = *(const float2*)(src);
        float2 fb = *(const float2*)(src + 8);
        uint32_t ha, la, hb, lb;
        split2(fa.x, fa.y, ha, la);
        split2(fb.x, fb.y, hb, lb);
        g_w2q[row * W2_GSTRIDE + kt * 4 + sub] = make_uint4(ha, hb, la, lb);
        if (bid == 39 && tid == 0) { g_done = 0u; g_max_out_i = 0; g_max_enh_i = 0; }
    }
}

// =====================================================================
// Kernel A: fused split-bf16 MLP via mma.sync  ->  ratio[m]
//   256 tokens/CTA, 250 CTAs, 512 threads; depth-2 X prefetch banks;
//   accumulator-interleaved MMA order.
// =====================================================================
#define TOK 256

#define SO_W2Q  0
#define SO_B1   36864
#define SO_B2   37376
#define SO_W3   37632
#define SO_SC   37888
#define SO_W1Q  38016
#define SO_H1H  38016
#define SO_H1L  107648
#define MLP_SMEM 177280

struct XB { float2 c00, c10, c20, c30, c01, c11, c21, c31; };

__device__ __forceinline__ void loadx(XB& x,
        const float* xr0, const float* xr8,
        const float* xr16, const float* xr24, int k0)
{
    x.c00 = *(const float2*)(xr0  + k0);  x.c01 = *(const float2*)(xr0  + k0 + 8);
    x.c10 = *(const float2*)(xr8  + k0);  x.c11 = *(const float2*)(xr8  + k0 + 8);
    x.c20 = *(const float2*)(xr16 + k0);  x.c21 = *(const float2*)(xr16 + k0 + 8);
    x.c30 = *(const float2*)(xr24 + k0);  x.c31 = *(const float2*)(xr24 + k0 + 8);
}

__device__ __forceinline__ void g1_step(XB& x, float acc[2][8][4],
        const uint4* w1q, int warp_n0, int tig, int kt, int ktn,
        const float* xr0, const float* xr8,
        const float* xr16, const float* xr24)
{
    uint32_t ah0[4], al0[4], ah1[4], al1[4];
    split2(x.c00.x, x.c00.y, ah0[0], al0[0]);
    split2(x.c10.x, x.c10.y, ah0[1], al0[1]);
    split2(x.c01.x, x.c01.y, ah0[2], al0[2]);
    split2(x.c11.x, x.c11.y, ah0[3], al0[3]);
    split2(x.c20.x, x.c20.y, ah1[0], al1[0]);
    split2(x.c30.x, x.c30.y, ah1[1], al1[1]);
    split2(x.c21.x, x.c21.y, ah1[2], al1[2]);
    split2(x.c31.x, x.c31.y, ah1[3], al1[3]);

    // refill this bank for kt+2 (clamped; redundant tail re-read is harmless)
    const int kn = (ktn < 16) ? ktn : 14;
    loadx(x, xr0, xr8, xr16, xr24, kn * 16 + tig * 2);

    const uint4* p = w1q + warp_n0 * W1_GSTRIDE + kt * 4 + tig;
    #pragma unroll
    for (int nt = 0; nt < 8; ++nt) {
        uint4 g = *p;
        p += 8 * W1_GSTRIDE;
        MMA(acc[0][nt], ah0, g.x, g.y);
        MMA(acc[1][nt], ah1, g.x, g.y);
        MMA(acc[0][nt], ah0, g.z, g.w);
        MMA(acc[1][nt], ah1, g.z, g.w);
        MMA(acc[0][nt], al0, g.x, g.y);
        MMA(acc[1][nt], al1, g.x, g.y);
    }
}

__global__ __launch_bounds__(512, 1)
void mlp_mma_kernel(const float* __restrict__ X,
                    const float* __restrict__ b1, const float* __restrict__ a1p,
                    const float* __restrict__ b2, const float* __restrict__ a2p,
                    const float* __restrict__ W3, const float* __restrict__ b3)
{
    extern __shared__ char sm[];
    const int tid  = threadIdx.x;
    const int wid  = tid >> 5;
    const int lane = tid & 31;
    const int grp  = lane >> 2;
    const int tig  = lane & 3;
    const int m0   = blockIdx.x * TOK;

    uint4* w1q = (uint4*)(sm + SO_W1Q);
    uint4* w2q = (uint4*)(sm + SO_W2Q);
    uint32_t* h1h = (uint32_t*)(sm + SO_H1H);
    uint32_t* h1l = (uint32_t*)(sm + SO_H1L);
    float* b1s = (float*)(sm + SO_B1);
    float* b2s = (float*)(sm + SO_B2);
    float* w3s = (float*)(sm + SO_W3);
    float* scl = (float*)(sm + SO_SC);

    // ---- stage biases / w3 row 2 / scalars ----
    if (tid < 128) b1s[tid] = b1[tid];
    else if (tid < 192) b2s[tid - 128] = b2[tid - 128];
    else if (tid < 256) w3s[tid - 192] = W3[2 * H2_ + (tid - 192)];
    if (tid == 0) { scl[0] = *a1p; scl[1] = *a2p; scl[2] = b3[2]; }

    // ---- copy pre-converted weight granules into smem ----
    #pragma unroll 4
    for (int i = tid; i < 128 * W1_GSTRIDE; i += 512) w1q[i] = g_w1q[i];
    #pragma unroll 2
    for (int i = tid; i < 64 * W2_GSTRIDE; i += 512) w2q[i] = g_w2q[i];
    __syncthreads();

    // ========= GEMM1: [256 x 256] * W1^T -> [256 x 128] =========
    const int wid_m  = wid >> 1;
    const int nhalf  = wid & 1;
    const int warp_n0 = nhalf * 64 + grp;
    const float* xr0  = X + (size_t)(m0 + wid_m * 32 + grp) * GRUH;
    const float* xr8  = xr0 + 8  * GRUH;
    const float* xr16 = xr0 + 16 * GRUH;
    const float* xr24 = xr0 + 24 * GRUH;

    float acc[2][8][4];
    #pragma unroll
    for (int t = 0; t < 2; ++t)
        #pragma unroll
        for (int nt = 0; nt < 8; ++nt)
            #pragma unroll
            for (int j = 0; j < 4; ++j) acc[t][nt][j] = 0.0f;

    XB xa, xb;
    loadx(xa, xr0, xr8, xr16, xr24, 0 * 16 + tig * 2);
    loadx(xb, xr0, xr8, xr16, xr24, 1 * 16 + tig * 2);

    #pragma unroll 1
    for (int kt = 0; kt < 16; kt += 2) {
        g1_step(xa, acc, w1q, warp_n0, tig, kt,     kt + 2, xr0, xr8, xr16, xr24);
        g1_step(xb, acc, w1q, warp_n0, tig, kt + 1, kt + 3, xr0, xr8, xr16, xr24);
    }
    __syncthreads();

    // ---- epilogue 1: bias + prelu, split hi/lo -> H1 smem ----
    {
        const float A1 = scl[0];
        const int rbase = wid_m * 32 + grp;
        #pragma unroll
        for (int t = 0; t < 2; ++t) {
            const int r = rbase + t * 16;
            #pragma unroll
            for (int nt = 0; nt < 8; ++nt) {
                const int col0 = nhalf * 64 + nt * 8 + tig * 2;
                float v00 = acc[t][nt][0] + b1s[col0];
                float v01 = acc[t][nt][1] + b1s[col0 + 1];
                float v80 = acc[t][nt][2] + b1s[col0];
                float v81 = acc[t][nt][3] + b1s[col0 + 1];
                v00 = (v00 >= 0.0f) ? v00 : A1 * v00;
                v01 = (v01 >= 0.0f) ? v01 : A1 * v01;
                v80 = (v80 >= 0.0f) ? v80 : A1 * v80;
                v81 = (v81 >= 0.0f) ? v81 : A1 * v81;
                uint32_t h0, l0, h8, l8;
                split2(v00, v01, h0, l0);
                split2(v80, v81, h8, l8);
                const int cw = nhalf * 32 + nt * 4 + tig;
                const int w0 = r * H1_WSTRIDE + cw;
                const int w8 = (r + 8) * H1_WSTRIDE + cw;
                h1h[w0] = h0; h1l[w0] = l0;
                h1h[w8] = h8; h1l[w8] = l8;
            }
        }
    }
    __syncthreads();

    // ========= GEMM2: [256 x 128] * W2^T -> [256 x 64] =========
    float acc2[8][4];
    #pragma unroll
    for (int nt = 0; nt < 8; ++nt)
        #pragma unroll
        for (int j = 0; j < 4; ++j) acc2[nt][j] = 0.0f;

    const int r0w = (wid * 16 + grp) * H1_WSTRIDE;
    const int r8w = (wid * 16 + grp + 8) * H1_WSTRIDE;

    #pragma unroll 1
    for (int kt = 0; kt < 8; ++kt) {
        const int wbase = kt * 8 + tig;
        uint32_t ah[4], al[4];
        ah[0] = h1h[r0w + wbase];     al[0] = h1l[r0w + wbase];
        ah[1] = h1h[r8w + wbase];     al[1] = h1l[r8w + wbase];
        ah[2] = h1h[r0w + wbase + 4]; al[2] = h1l[r0w + wbase + 4];
        ah[3] = h1h[r8w + wbase + 4]; al[3] = h1l[r8w + wbase + 4];
        const uint4* p = w2q + grp * W2_GSTRIDE + kt * 4 + tig;
        #pragma unroll
        for (int nt = 0; nt < 8; ++nt) {
            uint4 g = *p;
            p += 8 * W2_GSTRIDE;
            MMA(acc2[nt], ah, g.x, g.y);
            MMA(acc2[nt], ah, g.z, g.w);
            MMA(acc2[nt], al, g.x, g.y);
        }
    }

    // ---- epilogue 2: bias + prelu, dot w3, reduce over tig, softplus ----
    {
        const float A2 = scl[1];
        float p0 = 0.0f, p8 = 0.0f;
        #pragma unroll
        for (int nt = 0; nt < 8; ++nt) {
            const int col0 = nt * 8 + tig * 2;
            float v00 = acc2[nt][0] + b2s[col0];
            float v01 = acc2[nt][1] + b2s[col0 + 1];
            float v80 = acc2[nt][2] + b2s[col0];
            float v81 = acc2[nt][3] + b2s[col0 + 1];
            v00 = (v00 >= 0.0f) ? v00 : A2 * v00;
            v01 = (v01 >= 0.0f) ? v01 : A2 * v01;
            v80 = (v80 >= 0.0f) ? v80 : A2 * v80;
            v81 = (v81 >= 0.0f) ? v81 : A2 * v81;
            p0 = fmaf(v00, w3s[col0], fmaf(v01, w3s[col0 + 1], p0));
            p8 = fmaf(v80, w3s[col0], fmaf(v81, w3s[col0 + 1], p8));
        }
        p0 += __shfl_xor_sync(0xffffffffu, p0, 1);
        p0 += __shfl_xor_sync(0xffffffffu, p0, 2);
        p8 += __shfl_xor_sync(0xffffffffu, p8, 1);
        p8 += __shfl_xor_sync(0xffffffffu, p8, 2);
        if (tig == 0) {
            const float bb3 = scl[2];
            float pa = p0 + bb3;
            float pb = p8 + bb3;
            float spa = fmaxf(pa, 0.0f) + log1pf(expf(-fabsf(pa)));
            float spb = fmaxf(pb, 0.0f) + log1pf(expf(-fabsf(pb)));
            float ra = fminf(fmaxf(spa + 1.0f, 1.0f), 20.0f);
            float rb = fminf(fmaxf(spb + 1.0f, 1.0f), 20.0f);
            g_ratio[m0 + wid * 16 + grp]     = ra;
            g_ratio[m0 + wid * 16 + grp + 8] = rb;
        }
    }
}

// =====================================================================
// Kernel B: blocked IIR + fused device-wide normalize (unchanged R10)
// =====================================================================
#define CCHUNK 1280
#define CWARM  256
#define C_PB   (N_ / CCHUNK)      // 250 chunks per batch
#define CGRID  ((B_ * C_PB) / 8)  // 500 CTAs

__device__ __forceinline__ float interp_ratio(const float* __restrict__ rb, int n)
{
    float src = ((float)n + 0.5f) * 0.0125f - 0.5f;
    src = fminf(fmaxf(src, 0.0f), 3999.0f);
    float f0 = floorf(src);
    int   i0 = (int)f0;
    int   i1 = min(i0 + 1, 3999);
    float w  = src - f0;
    return rb[i0] * (1.0f - w) + rb[i1] * w;
}
__device__ __forceinline__ float gain_of(float x, float thr, float ratio)
{
    float env = fabsf(x);
    float gr  = (env > thr) ? (thr + __fdividef(env - thr, ratio)) : env;
    float g   = __fdividef(gr, env + 1e-8f);
    return fminf(fmaxf(g, 0.1f), 2.0f);
}

__global__ __launch_bounds__(256, 4)
void compress_kernel(const float* __restrict__ enh,
                     const float* __restrict__ noisy,
                     float* __restrict__ out)
{
    const int w    = (blockIdx.x * blockDim.x + threadIdx.x) >> 5;
    const int lane = threadIdx.x & 31;
    const int b     = w / C_PB;
    const int chunk = w % C_PB;
    const int t0    = chunk * CCHUNK;
    const int start = (chunk == 0) ? 0 : (t0 - CWARM);

    const float* eb = enh   + (size_t)b * N_;
    const float* nb = noisy + (size_t)b * N_;
    float*       ob = out   + (size_t)b * N_;
    const float* rb = g_ratio + b * T_;

    const float q   = 0.43046721f;                    // 0.9^8
    const float qi  = powf(q, (float)lane);
    const float q32 = 1.9342813113834067e-12f;        // 0.9^256

    float s_in_e, s_in_r;
    {
        float e  = eb[start];
        float nn = nb[start];
        float ratio = interp_ratio(rb, start);
        s_in_e = gain_of(e, 0.3f, ratio);
        s_in_r = gain_of(nn - e, 0.1f, ratio * 0.5f);
    }

    float mx_out = 0.0f, mx_enh = 0.0f;
    const int nend = t0 + CCHUNK;

    #pragma unroll 1
    for (int g0 = start; g0 < nend; g0 += 256) {
        const int n0 = g0 + lane * 8;
        float4 e0 = *(const float4*)(eb + n0);
        float4 e1 = *(const float4*)(eb + n0 + 4);
        float4 x0 = *(const float4*)(nb + n0);
        float4 x1 = *(const float4*)(nb + n0 + 4);
        float e[8] = {e0.x, e0.y, e0.z, e0.w, e1.x, e1.y, e1.z, e1.w};
        float x[8] = {x0.x, x0.y, x0.z, x0.w, x1.x, x1.y, x1.z, x1.w};

        float r[8], le[8], lr[8];
        float se = 0.0f, sr = 0.0f;
        #pragma unroll
        for (int j = 0; j < 8; ++j) {
            r[j] = x[j] - e[j];
            float ratio = interp_ratio(rb, n0 + j);
            float ge = gain_of(e[j], 0.3f, ratio);
            float gr = gain_of(r[j], 0.1f, ratio * 0.5f);
            se = fmaf(0.9f, se, 0.1f * ge);  le[j] = se;
            sr = fmaf(0.9f, sr, 0.1f * gr);  lr[j] = sr;
        }

        float Ie = se, Ir = sr, t;
        t = __shfl_up_sync(0xffffffffu, Ie, 1);  if (lane >= 1)  Ie = fmaf(0.43046721f,            t, Ie);
        t = __shfl_up_sync(0xffffffffu, Ir, 1);  if (lane >= 1)  Ir = fmaf(0.43046721f,            t, Ir);
        t = __shfl_up_sync(0xffffffffu, Ie, 2);  if (lane >= 2)  Ie = fmaf(0.1853020188851841f,    t, Ie);
        t = __shfl_up_sync(0xffffffffu, Ir, 2);  if (lane >= 2)  Ir = fmaf(0.1853020188851841f,    t, Ir);
        t = __shfl_up_sync(0xffffffffu, Ie, 4);  if (lane >= 4)  Ie = fmaf(0.03433683820292512f,   t, Ie);
        t = __shfl_up_sync(0xffffffffu, Ir, 4);  if (lane >= 4)  Ir = fmaf(0.03433683820292512f,   t, Ir);
        t = __shfl_up_sync(0xffffffffu, Ie, 8);  if (lane >= 8)  Ie = fmaf(0.001179018457773862f,  t, Ie);
        t = __shfl_up_sync(0xffffffffu, Ir, 8);  if (lane >= 8)  Ir = fmaf(0.001179018457773862f,  t, Ir);
        t = __shfl_up_sync(0xffffffffu, Ie, 16); if (lane >= 16) Ie = fmaf(1.390084523771456e-06f, t, Ie);
        t = __shfl_up_sync(0xffffffffu, Ir, 16); if (lane >= 16) Ir = fmaf(1.390084523771456e-06f, t, Ir);

        float ce = __shfl_up_sync(0xffffffffu, Ie, 1); if (lane == 0) ce = 0.0f;
        float cr = __shfl_up_sync(0xffffffffu, Ir, 1); if (lane == 0) cr = 0.0f;
        ce = fmaf(qi, s_in_e, ce);
        cr = fmaf(qi, s_in_r, cr);

        float Ie31 = __shfl_sync(0xffffffffu, Ie, 31);
        float Ir31 = __shfl_sync(0xffffffffu, Ir, 31);
        s_in_e = fmaf(q32, s_in_e, Ie31);
        s_in_r = fmaf(q32, s_in_r, Ir31);

        if (g0 >= t0) {
            const float d[8] = {0.9f, 0.81f, 0.729f, 0.6561f,
                                0.59049f, 0.531441f, 0.4782969f, 0.43046721f};
            float o[8];
            #pragma unroll
            for (int j = 0; j < 8; ++j) {
                float sej = fmaf(d[j], ce, le[j]);
                float srj = fmaf(d[j], cr, lr[j]);
                o[j] = fmaf(sej, e[j], 0.1f * (srj * r[j]));
                mx_out = fmaxf(mx_out, fabsf(o[j]));
                mx_enh = fmaxf(mx_enh, fabsf(e[j]));
            }
            *(float4*)(ob + n0)     = make_float4(o[0], o[1], o[2], o[3]);
            *(float4*)(ob + n0 + 4) = make_float4(o[4], o[5], o[6], o[7]);
        }
    }

    #pragma unroll
    for (int off = 16; off > 0; off >>= 1) {
        mx_out = fmaxf(mx_out, __shfl_xor_sync(0xffffffffu, mx_out, off));
        mx_enh = fmaxf(mx_enh, __shfl_xor_sync(0xffffffffu, mx_enh, off));
    }
    if (lane == 0) {
        atomicMax(&g_max_out_i, __float_as_int(mx_out));
        atomicMax(&g_max_enh_i, __float_as_int(mx_enh));
    }

    // ---- device-wide arrive + spin barrier (all 500 CTAs resident) ----
    __syncthreads();
    if (threadIdx.x == 0) {
        __threadfence();
        atomicAdd(&g_done, 1u);
        while (*(volatile unsigned*)&g_done < (unsigned)gridDim.x)
            __nanosleep(64);
    }
    __syncthreads();
    __threadfence();

    // ---- fused normalize: rescale this warp's own chunk (L2-hot) ----
    {
        const float mo = __int_as_float(*(volatile int*)&g_max_out_i);
        const float me = __int_as_float(*(volatile int*)&g_max_enh_i);
        const float s  = __fdividef(me, mo + 1e-8f);
        #pragma unroll 1
        for (int g0 = t0; g0 < nend; g0 += 256) {
            const int n0 = g0 + lane * 8;
            float4 v0 = *(float4*)(ob + n0);
            float4 v1 = *(float4*)(ob + n0 + 4);
            v0.x *= s; v0.y *= s; v0.z *= s; v0.w *= s;
            v1.x *= s; v1.y *= s; v1.z *= s; v1.w *= s;
            *(float4*)(ob + n0)     = v0;
            *(float4*)(ob + n0 + 4) = v1;
        }
    }
}

// =====================================================================
extern "C" void kernel_launch(void* const* d_in, const int* in_sizes, int n_in,
                              void* d_out, int out_size)
{
    const float* gru   = (const float*)d_in[0];
    const float* enh   = (const float*)d_in[1];
    const float* noisy = (const float*)d_in[2];
    const float* W1    = (const float*)d_in[3];
    const float* b1    = (const float*)d_in[4];
    const float* a1    = (const float*)d_in[5];
    const float* W2    = (const float*)d_in[6];
    const float* b2    = (const float*)d_in[7];
    const float* a2    = (const float*)d_in[8];
    const float* W3    = (const float*)d_in[9];
    const float* b3    = (const float*)d_in[10];
    float* out = (float*)d_out;

    cudaFuncSetAttribute(mlp_mma_kernel, cudaFuncAttributeMaxDynamicSharedMemorySize, MLP_SMEM);

    prep_kernel<<<40, 256>>>(W1, W2);
    mlp_mma_kernel<<<M_ / TOK, 512, MLP_SMEM>>>(gru, b1, a1, b2, a2, W3, b3);
    compress_kernel<<<CGRID, 256>>>(enh, noisy, out);
}

// round 14
// speedup vs baseline: 1.1815x; 1.0155x over previous
#include <cuda_runtime.h>
#include <cuda_bf16.h>
#include <math.h>
#include <stdint.h>

// ---------------- problem constants ----------------
#define B_    16
#define T_    4000
#define GRUH  256
#define H1_   128
#define H2_   64
#define N_    320000          // T_ * HOP(80)
#define M_    (B_ * T_)       // 64000 tokens

// ---------------- device scratch ----------------
__device__ float g_ratio[M_];
__device__ int   g_max_out_i;
__device__ int   g_max_enh_i;
__device__ unsigned g_done;
__device__ uint4 g_w1q[128 * 68];   // W1 hi/lo granules (gmem master copy)
__device__ uint4 g_w2q[64 * 36];    // W2 hi/lo granules

// =====================================================================
// helpers
// =====================================================================
__device__ __forceinline__ uint32_t pack_bf16x2(__nv_bfloat16 a, __nv_bfloat16 b) {
    return (uint32_t)__bfloat16_as_ushort(a) | ((uint32_t)__bfloat16_as_ushort(b) << 16);
}
__device__ __forceinline__ void split2(float v0, float v1, uint32_t& hi, uint32_t& lo) {
    __nv_bfloat16 h0 = __float2bfloat16_rn(v0);
    __nv_bfloat16 h1 = __float2bfloat16_rn(v1);
    float l0 = v0 - __bfloat162float(h0);
    float l1 = v1 - __bfloat162float(h1);
    hi = pack_bf16x2(h0, h1);
    lo = pack_bf16x2(__float2bfloat16_rn(l0), __float2bfloat16_rn(l1));
}
// m16n8k16 bf16 MMA, f32 accumulate (portable PTX, sm_80+)
__device__ __forceinline__ void mma_bf16_(float c[4], const uint32_t a[4],
                                          uint32_t b0, uint32_t b1) {
    asm volatile(
        "mma.sync.aligned.m16n8k16.row.col.f32.bf16.bf16.f32 "
        "{%0,%1,%2,%3}, {%4,%5,%6,%7}, {%8,%9}, {%0,%1,%2,%3};"
        : "+f"(c[0]), "+f"(c[1]), "+f"(c[2]), "+f"(c[3])
        : "r"(a[0]), "r"(a[1]), "r"(a[2]), "r"(a[3]), "r"(b0), "r"(b1));
}
#define MMA(c, a, b0, b1) mma_bf16_(c, a, b0, b1)

#define W1_GSTRIDE 68
#define W2_GSTRIDE 36
#define H1_WSTRIDE 68

// =====================================================================
// Kernel P: one-time weight conversion — 40 CTAs, one granule/thread
// =====================================================================
__global__ __launch_bounds__(256)
void prep_kernel(const float* __restrict__ W1, const float* __restrict__ W2)
{
    const int tid = threadIdx.x;
    const int bid = blockIdx.x;
    if (bid < 32) {
        const int gid = bid * 256 + tid;       // 0..8191
        const int row = gid >> 6;              // 0..127
        const int pos = gid & 63;
        const int kt = pos >> 2, sub = pos & 3;
        const float* src = W1 + (size_t)row * GRUH + kt * 16 + sub * 2;
        float2 fa = *(const float2*)(src);
        float2 fb = *(const float2*)(src + 8);
        uint32_t ha, la, hb, lb;
        split2(fa.x, fa.y, ha, la);
        split2(fb.x, fb.y, hb, lb);
        g_w1q[row * W1_GSTRIDE + kt * 4 + sub] = make_uint4(ha, hb, la, lb);
    } else {
        const int gid = (bid - 32) * 256 + tid; // 0..2047
        const int row = gid >> 5;               // 0..63
        const int pos = gid & 31;
        const int kt = pos >> 2, sub = pos & 3;
        const float* src = W2 + (size_t)row * H1_ + kt * 16 + sub * 2;
        float2 fa = *(const float2*)(src);
        float2 fb = *(const float2*)(src + 8);
        uint32_t ha, la, hb, lb;
        split2(fa.x, fa.y, ha, la);
        split2(fb.x, fb.y, hb, lb);
        g_w2q[row * W2_GSTRIDE + kt * 4 + sub] = make_uint4(ha, hb, la, lb);
        if (bid == 39 && tid == 0) { g_done = 0u; g_max_out_i = 0; g_max_enh_i = 0; }
    }
}

// =====================================================================
// Kernel A: fused split-bf16 MLP via mma.sync  ->  ratio[m]
//   256 tokens/CTA, 250 CTAs, 512 threads (proven R11 config).
//   H1 smem legally overlaps W1 (each CTA does exactly ONE tile).
// =====================================================================
#define TOK 256

#define SO_W2Q  0
#define SO_B1   36864
#define SO_B2   37376
#define SO_W3   37632
#define SO_SC   37888
#define SO_W1Q  38016
#define SO_H1H  38016
#define SO_H1L  107648
#define MLP_SMEM 177280

struct XB { float2 c00, c10, c20, c30, c01, c11, c21, c31; };

__device__ __forceinline__ void loadx(XB& x,
        const float* xr0, const float* xr8,
        const float* xr16, const float* xr24, int k0)
{
    x.c00 = *(const float2*)(xr0  + k0);  x.c01 = *(const float2*)(xr0  + k0 + 8);
    x.c10 = *(const float2*)(xr8  + k0);  x.c11 = *(const float2*)(xr8  + k0 + 8);
    x.c20 = *(const float2*)(xr16 + k0);  x.c21 = *(const float2*)(xr16 + k0 + 8);
    x.c30 = *(const float2*)(xr24 + k0);  x.c31 = *(const float2*)(xr24 + k0 + 8);
}

__device__ __forceinline__ void g1_step(XB& x, float acc[2][8][4],
        const uint4* w1q, int warp_n0, int tig, int kt, int ktn,
        const float* xr0, const float* xr8,
        const float* xr16, const float* xr24)
{
    uint32_t ah0[4], al0[4], ah1[4], al1[4];
    split2(x.c00.x, x.c00.y, ah0[0], al0[0]);
    split2(x.c10.x, x.c10.y, ah0[1], al0[1]);
    split2(x.c01.x, x.c01.y, ah0[2], al0[2]);
    split2(x.c11.x, x.c11.y, ah0[3], al0[3]);
    split2(x.c20.x, x.c20.y, ah1[0], al1[0]);
    split2(x.c30.x, x.c30.y, ah1[1], al1[1]);
    split2(x.c21.x, x.c21.y, ah1[2], al1[2]);
    split2(x.c31.x, x.c31.y, ah1[3], al1[3]);

    const int kn = (ktn < 16) ? ktn : 14;
    loadx(x, xr0, xr8, xr16, xr24, kn * 16 + tig * 2);

    const uint4* p = w1q + warp_n0 * W1_GSTRIDE + kt * 4 + tig;
    #pragma unroll
    for (int nt = 0; nt < 8; ++nt) {
        uint4 g = *p;
        p += 8 * W1_GSTRIDE;
        MMA(acc[0][nt], ah0, g.x, g.y);
        MMA(acc[1][nt], ah1, g.x, g.y);
        MMA(acc[0][nt], ah0, g.z, g.w);
        MMA(acc[1][nt], ah1, g.z, g.w);
        MMA(acc[0][nt], al0, g.x, g.y);
        MMA(acc[1][nt], al1, g.x, g.y);
    }
}

__global__ __launch_bounds__(512, 1)
void mlp_mma_kernel(const float* __restrict__ X,
                    const float* __restrict__ b1, const float* __restrict__ a1p,
                    const float* __restrict__ b2, const float* __restrict__ a2p,
                    const float* __restrict__ W3, const float* __restrict__ b3)
{
    extern __shared__ char sm[];
    const int tid  = threadIdx.x;
    const int wid  = tid >> 5;
    const int lane = tid & 31;
    const int grp  = lane >> 2;
    const int tig  = lane & 3;
    const int m0   = blockIdx.x * TOK;

    uint4* w1q = (uint4*)(sm + SO_W1Q);
    uint4* w2q = (uint4*)(sm + SO_W2Q);
    uint32_t* h1h = (uint32_t*)(sm + SO_H1H);
    uint32_t* h1l = (uint32_t*)(sm + SO_H1L);
    float* b1s = (float*)(sm + SO_B1);
    float* b2s = (float*)(sm + SO_B2);
    float* w3s = (float*)(sm + SO_W3);
    float* scl = (float*)(sm + SO_SC);

    // ---- stage biases / w3 row 2 / scalars ----
    if (tid < 128) b1s[tid] = b1[tid];
    else if (tid < 192) b2s[tid - 128] = b2[tid - 128];
    else if (tid < 256) w3s[tid - 192] = W3[2 * H2_ + (tid - 192)];
    if (tid == 0) { scl[0] = *a1p; scl[1] = *a2p; scl[2] = b3[2]; }

    // ---- copy pre-converted weight granules into smem ----
    #pragma unroll 4
    for (int i = tid; i < 128 * W1_GSTRIDE; i += 512) w1q[i] = g_w1q[i];
    #pragma unroll 2
    for (int i = tid; i < 64 * W2_GSTRIDE; i += 512) w2q[i] = g_w2q[i];
    __syncthreads();

    // ========= GEMM1: [256 x 256] * W1^T -> [256 x 128] =========
    const int wid_m  = wid >> 1;
    const int nhalf  = wid & 1;
    const int warp_n0 = nhalf * 64 + grp;
    const float* xr0  = X + (size_t)(m0 + wid_m * 32 + grp) * GRUH;
    const float* xr8  = xr0 + 8  * GRUH;
    const float* xr16 = xr0 + 16 * GRUH;
    const float* xr24 = xr0 + 24 * GRUH;

    float acc[2][8][4];
    #pragma unroll
    for (int t = 0; t < 2; ++t)
        #pragma unroll
        for (int nt = 0; nt < 8; ++nt)
            #pragma unroll
            for (int j = 0; j < 4; ++j) acc[t][nt][j] = 0.0f;

    XB xa, xb;
    loadx(xa, xr0, xr8, xr16, xr24, 0 * 16 + tig * 2);
    loadx(xb, xr0, xr8, xr16, xr24, 1 * 16 + tig * 2);

    #pragma unroll 1
    for (int kt = 0; kt < 16; kt += 2) {
        g1_step(xa, acc, w1q, warp_n0, tig, kt,     kt + 2, xr0, xr8, xr16, xr24);
        g1_step(xb, acc, w1q, warp_n0, tig, kt + 1, kt + 3, xr0, xr8, xr16, xr24);
    }
    __syncthreads();

    // ---- epilogue 1: bias + prelu, split hi/lo -> H1 smem (over dead W1) ----
    {
        const float A1 = scl[0];
        const int rbase = wid_m * 32 + grp;
        #pragma unroll
        for (int t = 0; t < 2; ++t) {
            const int r = rbase + t * 16;
            #pragma unroll
            for (int nt = 0; nt < 8; ++nt) {
                const int col0 = nhalf * 64 + nt * 8 + tig * 2;
                float v00 = acc[t][nt][0] + b1s[col0];
                float v01 = acc[t][nt][1] + b1s[col0 + 1];
                float v80 = acc[t][nt][2] + b1s[col0];
                float v81 = acc[t][nt][3] + b1s[col0 + 1];
                v00 = (v00 >= 0.0f) ? v00 : A1 * v00;
                v01 = (v01 >= 0.0f) ? v01 : A1 * v01;
                v80 = (v80 >= 0.0f) ? v80 : A1 * v80;
                v81 = (v81 >= 0.0f) ? v81 : A1 * v81;
                uint32_t h0, l0, h8, l8;
                split2(v00, v01, h0, l0);
                split2(v80, v81, h8, l8);
                const int cw = nhalf * 32 + nt * 4 + tig;
                const int w0 = r * H1_WSTRIDE + cw;
                const int w8 = (r + 8) * H1_WSTRIDE + cw;
                h1h[w0] = h0; h1l[w0] = l0;
                h1h[w8] = h8; h1l[w8] = l8;
            }
        }
    }
    __syncthreads();

    // ========= GEMM2: [256 x 128] * W2^T -> [256 x 64] =========
    float acc2[8][4];
    #pragma unroll
    for (int nt = 0; nt < 8; ++nt)
        #pragma unroll
        for (int j = 0; j < 4; ++j) acc2[nt][j] = 0.0f;

    const int r0w = (wid * 16 + grp) * H1_WSTRIDE;
    const int r8w = (wid * 16 + grp + 8) * H1_WSTRIDE;

    #pragma unroll 1
    for (int kt = 0; kt < 8; ++kt) {
        const int wbase = kt * 8 + tig;
        uint32_t ah[4], al[4];
        ah[0] = h1h[r0w + wbase];     al[0] = h1l[r0w + wbase];
        ah[1] = h1h[r8w + wbase];     al[1] = h1l[r8w + wbase];
        ah[2] = h1h[r0w + wbase + 4]; al[2] = h1l[r0w + wbase + 4];
        ah[3] = h1h[r8w + wbase + 4]; al[3] = h1l[r8w + wbase + 4];
        const uint4* p = w2q + grp * W2_GSTRIDE + kt * 4 + tig;
        #pragma unroll
        for (int nt = 0; nt < 8; ++nt) {
            uint4 g = *p;
            p += 8 * W2_GSTRIDE;
            MMA(acc2[nt], ah, g.x, g.y);
            MMA(acc2[nt], ah, g.z, g.w);
            MMA(acc2[nt], al, g.x, g.y);
        }
    }

    // ---- epilogue 2: bias + prelu, dot w3, reduce over tig, softplus ----
    {
        const float A2 = scl[1];
        float p0 = 0.0f, p8 = 0.0f;
        #pragma unroll
        for (int nt = 0; nt < 8; ++nt) {
            const int col0 = nt * 8 + tig * 2;
            float v00 = acc2[nt][0] + b2s[col0];
            float v01 = acc2[nt][1] + b2s[col0 + 1];
            float v80 = acc2[nt][2] + b2s[col0];
            float v81 = acc2[nt][3] + b2s[col0 + 1];
            v00 = (v00 >= 0.0f) ? v00 : A2 * v00;
            v01 = (v01 >= 0.0f) ? v01 : A2 * v01;
            v80 = (v80 >= 0.0f) ? v80 : A2 * v80;
            v81 = (v81 >= 0.0f) ? v81 : A2 * v81;
            p0 = fmaf(v00, w3s[col0], fmaf(v01, w3s[col0 + 1], p0));
            p8 = fmaf(v80, w3s[col0], fmaf(v81, w3s[col0 + 1], p8));
        }
        p0 += __shfl_xor_sync(0xffffffffu, p0, 1);
        p0 += __shfl_xor_sync(0xffffffffu, p0, 2);
        p8 += __shfl_xor_sync(0xffffffffu, p8, 1);
        p8 += __shfl_xor_sync(0xffffffffu, p8, 2);
        if (tig == 0) {
            const float bb3 = scl[2];
            float pa = p0 + bb3;
            float pb = p8 + bb3;
            float spa = fmaxf(pa, 0.0f) + log1pf(expf(-fabsf(pa)));
            float spb = fmaxf(pb, 0.0f) + log1pf(expf(-fabsf(pb)));
            float ra = fminf(fmaxf(spa + 1.0f, 1.0f), 20.0f);
            float rb = fminf(fmaxf(spb + 1.0f, 1.0f), 20.0f);
            g_ratio[m0 + wid * 16 + grp]     = ra;
            g_ratio[m0 + wid * 16 + grp + 8] = rb;
        }
    }
}

// =====================================================================
// Kernel B: blocked IIR + fused normalize, outputs retained in SMEM
// across the device barrier (one gmem write instead of write+read+write)
// =====================================================================
#define CCHUNK 1280
#define CWARM  256
#define C_PB   (N_ / CCHUNK)      // 250 chunks per batch
#define CGRID  ((B_ * C_PB) / 8)  // 500 CTAs

__device__ __forceinline__ float interp_ratio(const float* __restrict__ rb, int n)
{
    float src = ((float)n + 0.5f) * 0.0125f - 0.5f;
    src = fminf(fmaxf(src, 0.0f), 3999.0f);
    float f0 = floorf(src);
    int   i0 = (int)f0;
    int   i1 = min(i0 + 1, 3999);
    float w  = src - f0;
    return rb[i0] * (1.0f - w) + rb[i1] * w;
}
__device__ __forceinline__ float gain_of(float x, float thr, float ratio)
{
    float env = fabsf(x);
    float gr  = (env > thr) ? (thr + __fdividef(env - thr, ratio)) : env;
    float g   = __fdividef(gr, env + 1e-8f);
    return fminf(fmaxf(g, 0.1f), 2.0f);
}

__global__ __launch_bounds__(256, 4)
void compress_kernel(const float* __restrict__ enh,
                     const float* __restrict__ noisy,
                     float* __restrict__ out)
{
    __shared__ float s_o[8][CCHUNK];   // 40 KB: per-warp chunk outputs

    const int wcta = threadIdx.x >> 5;
    const int w    = (blockIdx.x * blockDim.x + threadIdx.x) >> 5;
    const int lane = threadIdx.x & 31;
    const int b     = w / C_PB;
    const int chunk = w % C_PB;
    const int t0    = chunk * CCHUNK;
    const int start = (chunk == 0) ? 0 : (t0 - CWARM);

    const float* eb = enh   + (size_t)b * N_;
    const float* nb = noisy + (size_t)b * N_;
    float*       ob = out   + (size_t)b * N_;
    const float* rb = g_ratio + b * T_;

    const float q   = 0.43046721f;                    // 0.9^8
    const float qi  = powf(q, (float)lane);
    const float q32 = 1.9342813113834067e-12f;        // 0.9^256

    float s_in_e, s_in_r;
    {
        float e  = eb[start];
        float nn = nb[start];
        float ratio = interp_ratio(rb, start);
        s_in_e = gain_of(e, 0.3f, ratio);
        s_in_r = gain_of(nn - e, 0.1f, ratio * 0.5f);
    }

    float mx_out = 0.0f, mx_enh = 0.0f;
    const int nend = t0 + CCHUNK;

    #pragma unroll 1
    for (int g0 = start; g0 < nend; g0 += 256) {
        const int n0 = g0 + lane * 8;
        float4 e0 = *(const float4*)(eb + n0);
        float4 e1 = *(const float4*)(eb + n0 + 4);
        float4 x0 = *(const float4*)(nb + n0);
        float4 x1 = *(const float4*)(nb + n0 + 4);
        float e[8] = {e0.x, e0.y, e0.z, e0.w, e1.x, e1.y, e1.z, e1.w};
        float x[8] = {x0.x, x0.y, x0.z, x0.w, x1.x, x1.y, x1.z, x1.w};

        float r[8], le[8], lr[8];
        float se = 0.0f, sr = 0.0f;
        #pragma unroll
        for (int j = 0; j < 8; ++j) {
            r[j] = x[j] - e[j];
            float ratio = interp_ratio(rb, n0 + j);
            float ge = gain_of(e[j], 0.3f, ratio);
            float gr = gain_of(r[j], 0.1f, ratio * 0.5f);
            se = fmaf(0.9f, se, 0.1f * ge);  le[j] = se;
            sr = fmaf(0.9f, sr, 0.1f * gr);  lr[j] = sr;
        }

        float Ie = se, Ir = sr, t;
        t = __shfl_up_sync(0xffffffffu, Ie, 1);  if (lane >= 1)  Ie = fmaf(0.43046721f,            t, Ie);
        t = __shfl_up_sync(0xffffffffu, Ir, 1);  if (lane >= 1)  Ir = fmaf(0.43046721f,            t, Ir);
        t = __shfl_up_sync(0xffffffffu, Ie, 2);  if (lane >= 2)  Ie = fmaf(0.1853020188851841f,    t, Ie);
        t = __shfl_up_sync(0xffffffffu, Ir, 2);  if (lane >= 2)  Ir = fmaf(0.1853020188851841f,    t, Ir);
        t = __shfl_up_sync(0xffffffffu, Ie, 4);  if (lane >= 4)  Ie = fmaf(0.03433683820292512f,   t, Ie);
        t = __shfl_up_sync(0xffffffffu, Ir, 4);  if (lane >= 4)  Ir = fmaf(0.03433683820292512f,   t, Ir);
        t = __shfl_up_sync(0xffffffffu, Ie, 8);  if (lane >= 8)  Ie = fmaf(0.001179018457773862f,  t, Ie);
        t = __shfl_up_sync(0xffffffffu, Ir, 8);  if (lane >= 8)  Ir = fmaf(0.001179018457773862f,  t, Ir);
        t = __shfl_up_sync(0xffffffffu, Ie, 16); if (lane >= 16) Ie = fmaf(1.390084523771456e-06f, t, Ie);
        t = __shfl_up_sync(0xffffffffu, Ir, 16); if (lane >= 16) Ir = fmaf(1.390084523771456e-06f, t, Ir);

        float ce = __shfl_up_sync(0xffffffffu, Ie, 1); if (lane == 0) ce = 0.0f;
        float cr = __shfl_up_sync(0xffffffffu, Ir, 1); if (lane == 0) cr = 0.0f;
        ce = fmaf(qi, s_in_e, ce);
        cr = fmaf(qi, s_in_r, cr);

        float Ie31 = __shfl_sync(0xffffffffu, Ie, 31);
        float Ir31 = __shfl_sync(0xffffffffu, Ir, 31);
        s_in_e = fmaf(q32, s_in_e, Ie31);
        s_in_r = fmaf(q32, s_in_r, Ir31);

        if (g0 >= t0) {
            const float d[8] = {0.9f, 0.81f, 0.729f, 0.6561f,
                                0.59049f, 0.531441f, 0.4782969f, 0.43046721f};
            float* so = &s_o[wcta][n0 - t0];
            #pragma unroll
            for (int j = 0; j < 8; ++j) {
                float sej = fmaf(d[j], ce, le[j]);
                float srj = fmaf(d[j], cr, lr[j]);
                float o = fmaf(sej, e[j], 0.1f * (srj * r[j]));
                so[j] = o;
                mx_out = fmaxf(mx_out, fabsf(o));
                mx_enh = fmaxf(mx_enh, fabsf(e[j]));
            }
        }
    }

    #pragma unroll
    for (int off = 16; off > 0; off >>= 1) {
        mx_out = fmaxf(mx_out, __shfl_xor_sync(0xffffffffu, mx_out, off));
        mx_enh = fmaxf(mx_enh, __shfl_xor_sync(0xffffffffu, mx_enh, off));
    }
    if (lane == 0) {
        atomicMax(&g_max_out_i, __float_as_int(mx_out));
        atomicMax(&g_max_enh_i, __float_as_int(mx_enh));
    }

    // ---- device-wide arrive + spin barrier (all 500 CTAs resident) ----
    __syncthreads();
    if (threadIdx.x == 0) {
        __threadfence();
        atomicAdd(&g_done, 1u);
        while (*(volatile unsigned*)&g_done < (unsigned)gridDim.x)
            __nanosleep(64);
    }
    __syncthreads();

    // ---- scale from smem, single gmem write ----
    {
        const float mo = __int_as_float(*(volatile int*)&g_max_out_i);
        const float me = __int_as_float(*(volatile int*)&g_max_enh_i);
        const float s  = __fdividef(me, mo + 1e-8f);
        #pragma unroll 1
        for (int off = lane * 8; off < CCHUNK; off += 256) {
            const float* so = &s_o[wcta][off];
            float4 v0 = make_float4(so[0] * s, so[1] * s, so[2] * s, so[3] * s);
            float4 v1 = make_float4(so[4] * s, so[5] * s, so[6] * s, so[7] * s);
            *(float4*)(ob + t0 + off)     = v0;
            *(float4*)(ob + t0 + off + 4) = v1;
        }
    }
}

// =====================================================================
extern "C" void kernel_launch(void* const* d_in, const int* in_sizes, int n_in,
                              void* d_out, int out_size)
{
    const float* gru   = (const float*)d_in[0];
    const float* enh   = (const float*)d_in[1];
    const float* noisy = (const float*)d_in[2];
    const float* W1    = (const float*)d_in[3];
    const float* b1    = (const float*)d_in[4];
    const float* a1    = (const float*)d_in[5];
    const float* W2    = (const float*)d_in[6];
    const float* b2    = (const float*)d_in[7];
    const float* a2    = (const float*)d_in[8];
    const float* W3    = (const float*)d_in[9];
    const float* b3    = (const float*)d_in[10];
    float* out = (float*)d_out;

    cudaFuncSetAttribute(mlp_mma_kernel, cudaFuncAttributeMaxDynamicSharedMemorySize, MLP_SMEM);

    prep_kernel<<<40, 256>>>(W1, W2);
    mlp_mma_kernel<<<M_ / TOK, 512, MLP_SMEM>>>(gru, b1, a1, b2, a2, W3, b3);
    compress_kernel<<<CGRID, 256>>>(enh, noisy, out);
}

// round 16
// speedup vs baseline: 1.2075x; 1.0220x over previous
#include <cuda_runtime.h>
#include <cuda_bf16.h>
#include <math.h>
#include <stdint.h>

// ---------------- problem constants ----------------
#define B_    16
#define T_    4000
#define GRUH  256
#define H1_   128
#define H2_   64
#define N_    320000          // T_ * HOP(80)
#define M_    (B_ * T_)       // 64000 tokens

// ---------------- device scratch ----------------
__device__ float g_ratio[M_];
__device__ int   g_max_out_i;
__device__ int   g_max_enh_i;
__device__ unsigned g_done;
__device__ uint4 g_w1q[128 * 68];   // W1 hi/lo granules (gmem master copy)
__device__ uint4 g_w2q[64 * 36];    // W2 hi/lo granules

// =====================================================================
// helpers
// =====================================================================
__device__ __forceinline__ uint32_t pack_bf16x2(__nv_bfloat16 a, __nv_bfloat16 b) {
    return (uint32_t)__bfloat16_as_ushort(a) | ((uint32_t)__bfloat16_as_ushort(b) << 16);
}
__device__ __forceinline__ void split2(float v0, float v1, uint32_t& hi, uint32_t& lo) {
    __nv_bfloat16 h0 = __float2bfloat16_rn(v0);
    __nv_bfloat16 h1 = __float2bfloat16_rn(v1);
    float l0 = v0 - __bfloat162float(h0);
    float l1 = v1 - __bfloat162float(h1);
    hi = pack_bf16x2(h0, h1);
    lo = pack_bf16x2(__float2bfloat16_rn(l0), __float2bfloat16_rn(l1));
}
// m16n8k16 bf16 MMA, f32 accumulate (portable PTX, sm_80+)
__device__ __forceinline__ void mma_bf16_(float c[4], const uint32_t a[4],
                                          uint32_t b0, uint32_t b1) {
    asm volatile(
        "mma.sync.aligned.m16n8k16.row.col.f32.bf16.bf16.f32 "
        "{%0,%1,%2,%3}, {%4,%5,%6,%7}, {%8,%9}, {%0,%1,%2,%3};"
        : "+f"(c[0]), "+f"(c[1]), "+f"(c[2]), "+f"(c[3])
        : "r"(a[0]), "r"(a[1]), "r"(a[2]), "r"(a[3]), "r"(b0), "r"(b1));
}
#define MMA(c, a, b0, b1) mma_bf16_(c, a, b0, b1)

#define W1_GSTRIDE 68
#define W2_GSTRIDE 36
#define H1_WSTRIDE 68

// =====================================================================
// Kernel P: one-time weight conversion — 40 CTAs, one granule/thread
// =====================================================================
__global__ __launch_bounds__(256)
void prep_kernel(const float* __restrict__ W1, const float* __restrict__ W2)
{
    const int tid = threadIdx.x;
    const int bid = blockIdx.x;
    if (bid < 32) {
        const int gid = bid * 256 + tid;       // 0..8191
        const int row = gid >> 6;              // 0..127
        const int pos = gid & 63;
        const int kt = pos >> 2, sub = pos & 3;
        const float* src = W1 + (size_t)row * GRUH + kt * 16 + sub * 2;
        float2 fa = *(const float2*)(src);
        float2 fb = *(const float2*)(src + 8);
        uint32_t ha, la, hb, lb;
        split2(fa.x, fa.y, ha, la);
        split2(fb.x, fb.y, hb, lb);
        g_w1q[row * W1_GSTRIDE + kt * 4 + sub] = make_uint4(ha, hb, la, lb);
    } else {
        const int gid = (bid - 32) * 256 + tid; // 0..2047
        const int row = gid >> 5;               // 0..63
        const int pos = gid & 31;
        const int kt = pos >> 2, sub = pos & 3;
        const float* src = W2 + (size_t)row * H1_ + kt * 16 + sub * 2;
        float2 fa = *(const float2*)(src);
        float2 fb = *(const float2*)(src + 8);
        uint32_t ha, la, hb, lb;
        split2(fa.x, fa.y, ha, la);
        split2(fb.x, fb.y, hb, lb);
        g_w2q[row * W2_GSTRIDE + kt * 4 + sub] = make_uint4(ha, hb, la, lb);
        if (bid == 39 && tid == 0) { g_done = 0u; g_max_out_i = 0; g_max_enh_i = 0; }
    }
}

// =====================================================================
// Kernel A: fused split-bf16 (3-term) MLP via mma.sync -> ratio[m]
//   256 tokens/CTA, 250 CTAs, 512 threads (proven R13 config).
// =====================================================================
#define TOK 256

#define SO_W2Q  0
#define SO_B1   36864
#define SO_B2   37376
#define SO_W3   37632
#define SO_SC   37888
#define SO_W1Q  38016
#define SO_H1H  38016
#define SO_H1L  107648
#define MLP_SMEM 177280

struct XB { float2 c00, c10, c20, c30, c01, c11, c21, c31; };

__device__ __forceinline__ void loadx(XB& x,
        const float* xr0, const float* xr8,
        const float* xr16, const float* xr24, int k0)
{
    x.c00 = *(const float2*)(xr0  + k0);  x.c01 = *(const float2*)(xr0  + k0 + 8);
    x.c10 = *(const float2*)(xr8  + k0);  x.c11 = *(const float2*)(xr8  + k0 + 8);
    x.c20 = *(const float2*)(xr16 + k0);  x.c21 = *(const float2*)(xr16 + k0 + 8);
    x.c30 = *(const float2*)(xr24 + k0);  x.c31 = *(const float2*)(xr24 + k0 + 8);
}

__device__ __forceinline__ void g1_step(XB& x, float acc[2][8][4],
        const uint4* w1q, int warp_n0, int tig, int kt, int ktn,
        const float* xr0, const float* xr8,
        const float* xr16, const float* xr24)
{
    uint32_t ah0[4], al0[4], ah1[4], al1[4];
    split2(x.c00.x, x.c00.y, ah0[0], al0[0]);
    split2(x.c10.x, x.c10.y, ah0[1], al0[1]);
    split2(x.c01.x, x.c01.y, ah0[2], al0[2]);
    split2(x.c11.x, x.c11.y, ah0[3], al0[3]);
    split2(x.c20.x, x.c20.y, ah1[0], al1[0]);
    split2(x.c30.x, x.c30.y, ah1[1], al1[1]);
    split2(x.c21.x, x.c21.y, ah1[2], al1[2]);
    split2(x.c31.x, x.c31.y, ah1[3], al1[3]);

    const int kn = (ktn < 16) ? ktn : 14;
    loadx(x, xr0, xr8, xr16, xr24, kn * 16 + tig * 2);

    const uint4* p = w1q + warp_n0 * W1_GSTRIDE + kt * 4 + tig;
    #pragma unroll
    for (int nt = 0; nt < 8; ++nt) {
        uint4 g = *p;
        p += 8 * W1_GSTRIDE;
        MMA(acc[0][nt], ah0, g.x, g.y);
        MMA(acc[1][nt], ah1, g.x, g.y);
        MMA(acc[0][nt], ah0, g.z, g.w);
        MMA(acc[1][nt], ah1, g.z, g.w);
        MMA(acc[0][nt], al0, g.x, g.y);
        MMA(acc[1][nt], al1, g.x, g.y);
    }
}

__global__ __launch_bounds__(512, 1)
void mlp_mma_kernel(const float* __restrict__ X,
                    const float* __restrict__ b1, const float* __restrict__ a1p,
                    const float* __restrict__ b2, const float* __restrict__ a2p,
                    const float* __restrict__ W3, const float* __restrict__ b3)
{
    extern __shared__ char sm[];
    const int tid  = threadIdx.x;
    const int wid  = tid >> 5;
    const int lane = tid & 31;
    const int grp  = lane >> 2;
    const int tig  = lane & 3;
    const int m0   = blockIdx.x * TOK;

    uint4* w1q = (uint4*)(sm + SO_W1Q);
    uint4* w2q = (uint4*)(sm + SO_W2Q);
    uint32_t* h1h = (uint32_t*)(sm + SO_H1H);
    uint32_t* h1l = (uint32_t*)(sm + SO_H1L);
    float* b1s = (float*)(sm + SO_B1);
    float* b2s = (float*)(sm + SO_B2);
    float* w3s = (float*)(sm + SO_W3);
    float* scl = (float*)(sm + SO_SC);

    // ---- stage biases / w3 row 2 / scalars ----
    if (tid < 128) b1s[tid] = b1[tid];
    else if (tid < 192) b2s[tid - 128] = b2[tid - 128];
    else if (tid < 256) w3s[tid - 192] = W3[2 * H2_ + (tid - 192)];
    if (tid == 0) { scl[0] = *a1p; scl[1] = *a2p; scl[2] = b3[2]; }

    // ---- copy pre-converted weight granules into smem ----
    #pragma unroll 4
    for (int i = tid; i < 128 * W1_GSTRIDE; i += 512) w1q[i] = g_w1q[i];
    #pragma unroll 2
    for (int i = tid; i < 64 * W2_GSTRIDE; i += 512) w2q[i] = g_w2q[i];
    __syncthreads();

    // ========= GEMM1: [256 x 256] * W1^T -> [256 x 128] =========
    const int wid_m  = wid >> 1;
    const int nhalf  = wid & 1;
    const int warp_n0 = nhalf * 64 + grp;
    const float* xr0  = X + (size_t)(m0 + wid_m * 32 + grp) * GRUH;
    const float* xr8  = xr0 + 8  * GRUH;
    const float* xr16 = xr0 + 16 * GRUH;
    const float* xr24 = xr0 + 24 * GRUH;

    float acc[2][8][4];
    #pragma unroll
    for (int t = 0; t < 2; ++t)
        #pragma unroll
        for (int nt = 0; nt < 8; ++nt)
            #pragma unroll
            for (int j = 0; j < 4; ++j) acc[t][nt][j] = 0.0f;

    XB xa, xb;
    loadx(xa, xr0, xr8, xr16, xr24, 0 * 16 + tig * 2);
    loadx(xb, xr0, xr8, xr16, xr24, 1 * 16 + tig * 2);

    #pragma unroll 1
    for (int kt = 0; kt < 16; kt += 2) {
        g1_step(xa, acc, w1q, warp_n0, tig, kt,     kt + 2, xr0, xr8, xr16, xr24);
        g1_step(xb, acc, w1q, warp_n0, tig, kt + 1, kt + 3, xr0, xr8, xr16, xr24);
    }
    __syncthreads();

    // ---- epilogue 1: bias + prelu, split hi/lo -> H1 smem (over dead W1) ----
    {
        const float A1 = scl[0];
        const int rbase = wid_m * 32 + grp;
        #pragma unroll
        for (int t = 0; t < 2; ++t) {
            const int r = rbase + t * 16;
            #pragma unroll
            for (int nt = 0; nt < 8; ++nt) {
                const int col0 = nhalf * 64 + nt * 8 + tig * 2;
                float v00 = acc[t][nt][0] + b1s[col0];
                float v01 = acc[t][nt][1] + b1s[col0 + 1];
                float v80 = acc[t][nt][2] + b1s[col0];
                float v81 = acc[t][nt][3] + b1s[col0 + 1];
                v00 = (v00 >= 0.0f) ? v00 : A1 * v00;
                v01 = (v01 >= 0.0f) ? v01 : A1 * v01;
                v80 = (v80 >= 0.0f) ? v80 : A1 * v80;
                v81 = (v81 >= 0.0f) ? v81 : A1 * v81;
                uint32_t h0, l0, h8, l8;
                split2(v00, v01, h0, l0);
                split2(v80, v81, h8, l8);
                const int cw = nhalf * 32 + nt * 4 + tig;
                const int w0 = r * H1_WSTRIDE + cw;
                const int w8 = (r + 8) * H1_WSTRIDE + cw;
                h1h[w0] = h0; h1l[w0] = l0;
                h1h[w8] = h8; h1l[w8] = l8;
            }
        }
    }
    __syncthreads();

    // ========= GEMM2: [256 x 128] * W2^T -> [256 x 64] =========
    float acc2[8][4];
    #pragma unroll
    for (int nt = 0; nt < 8; ++nt)
        #pragma unroll
        for (int j = 0; j < 4; ++j) acc2[nt][j] = 0.0f;

    const int r0w = (wid * 16 + grp) * H1_WSTRIDE;
    const int r8w = (wid * 16 + grp + 8) * H1_WSTRIDE;

    #pragma unroll 1
    for (int kt = 0; kt < 8; ++kt) {
        const int wbase = kt * 8 + tig;
        uint32_t ah[4], al[4];
        ah[0] = h1h[r0w + wbase];     al[0] = h1l[r0w + wbase];
        ah[1] = h1h[r8w + wbase];     al[1] = h1l[r8w + wbase];
        ah[2] = h1h[r0w + wbase + 4]; al[2] = h1l[r0w + wbase + 4];
        ah[3] = h1h[r8w + wbase + 4]; al[3] = h1l[r8w + wbase + 4];
        const uint4* p = w2q + grp * W2_GSTRIDE + kt * 4 + tig;
        #pragma unroll
        for (int nt = 0; nt < 8; ++nt) {
            uint4 g = *p;
            p += 8 * W2_GSTRIDE;
            MMA(acc2[nt], ah, g.x, g.y);
            MMA(acc2[nt], ah, g.z, g.w);
            MMA(acc2[nt], al, g.x, g.y);
        }
    }

    // ---- epilogue 2: bias + prelu, dot w3, reduce over tig, softplus ----
    {
        const float A2 = scl[1];
        float p0 = 0.0f, p8 = 0.0f;
        #pragma unroll
        for (int nt = 0; nt < 8; ++nt) {
            const int col0 = nt * 8 + tig * 2;
            float v00 = acc2[nt][0] + b2s[col0];
            float v01 = acc2[nt][1] + b2s[col0 + 1];
            float v80 = acc2[nt][2] + b2s[col0];
            float v81 = acc2[nt][3] + b2s[col0 + 1];
            v00 = (v00 >= 0.0f) ? v00 : A2 * v00;
            v01 = (v01 >= 0.0f) ? v01 : A2 * v01;
            v80 = (v80 >= 0.0f) ? v80 : A2 * v80;
            v81 = (v81 >= 0.0f) ? v81 : A2 * v81;
            p0 = fmaf(v00, w3s[col0], fmaf(v01, w3s[col0 + 1], p0));
            p8 = fmaf(v80, w3s[col0], fmaf(v81, w3s[col0 + 1], p8));
        }
        p0 += __shfl_xor_sync(0xffffffffu, p0, 1);
        p0 += __shfl_xor_sync(0xffffffffu, p0, 2);
        p8 += __shfl_xor_sync(0xffffffffu, p8, 1);
        p8 += __shfl_xor_sync(0xffffffffu, p8, 2);
        if (tig == 0) {
            const float bb3 = scl[2];
            float pa = p0 + bb3;
            float pb = p8 + bb3;
            float spa = fmaxf(pa, 0.0f) + log1pf(expf(-fabsf(pa)));
            float spb = fmaxf(pb, 0.0f) + log1pf(expf(-fabsf(pb)));
            float ra = fminf(fmaxf(spa + 1.0f, 1.0f), 20.0f);
            float rb = fminf(fmaxf(spb + 1.0f, 1.0f), 20.0f);
            g_ratio[m0 + wid * 16 + grp]     = ra;
            g_ratio[m0 + wid * 16 + grp + 8] = rb;
        }
    }
}

// =====================================================================
// Kernel B: blocked IIR + fused normalize (smem-retained outputs).
//   NEW: ratio-table loads hoisted (4 per 8-sample group instead of 16),
//   and gain computed with ONE divide via algebraic merge.
// =====================================================================
#define CCHUNK 1280
#define CWARM  256
#define C_PB   (N_ / CCHUNK)      // 250 chunks per batch
#define CGRID  ((B_ * C_PB) / 8)  // 500 CTAs

__device__ __forceinline__ float interp_ratio(const float* __restrict__ rb, int n)
{
    float src = ((float)n + 0.5f) * 0.0125f - 0.5f;
    src = fminf(fmaxf(src, 0.0f), 3999.0f);
    float f0 = floorf(src);
    int   i0 = (int)f0;
    int   i1 = min(i0 + 1, 3999);
    float w  = src - f0;
    return rb[i0] * (1.0f - w) + rb[i1] * w;
}
// merged single-divide gain:
//   env>thr:  g = (thr*ratio - thr + env) / (ratio*(env+eps))
//   else:     g = env / (env+eps)
__device__ __forceinline__ float gain_of(float x, float thr, float ratio)
{
    float env = fabsf(x);
    bool  over = env > thr;
    float num = over ? fmaf(thr, ratio - 1.0f, env) : env;
    float den = over ? ratio * (env + 1e-8f) : (env + 1e-8f);
    float g = __fdividef(num, den);
    return fminf(fmaxf(g, 0.1f), 2.0f);
}

__global__ __launch_bounds__(256, 4)
void compress_kernel(const float* __restrict__ enh,
                     const float* __restrict__ noisy,
                     float* __restrict__ out)
{
    __shared__ float s_o[8][CCHUNK];   // 40 KB: per-warp chunk outputs

    const int wcta = threadIdx.x >> 5;
    const int w    = (blockIdx.x * blockDim.x + threadIdx.x) >> 5;
    const int lane = threadIdx.x & 31;
    const int b     = w / C_PB;
    const int chunk = w % C_PB;
    const int t0    = chunk * CCHUNK;
    const int start = (chunk == 0) ? 0 : (t0 - CWARM);

    const float* eb = enh   + (size_t)b * N_;
    const float* nb = noisy + (size_t)b * N_;
    float*       ob = out   + (size_t)b * N_;
    const float* rb = g_ratio + b * T_;

    const float q   = 0.43046721f;                    // 0.9^8
    const float qi  = powf(q, (float)lane);
    const float q32 = 1.9342813113834067e-12f;        // 0.9^256

    float s_in_e, s_in_r;
    {
        float e  = eb[start];
        float nn = nb[start];
        float ratio = interp_ratio(rb, start);
        s_in_e = gain_of(e, 0.3f, ratio);
        s_in_r = gain_of(nn - e, 0.1f, ratio * 0.5f);
    }

    float mx_out = 0.0f, mx_enh = 0.0f;
    const int nend = t0 + CCHUNK;

    #pragma unroll 1
    for (int g0 = start; g0 < nend; g0 += 256) {
        const int n0 = g0 + lane * 8;
        float4 e0 = *(const float4*)(eb + n0);
        float4 e1 = *(const float4*)(eb + n0 + 4);
        float4 x0 = *(const float4*)(nb + n0);
        float4 x1 = *(const float4*)(nb + n0 + 4);
        float e[8] = {e0.x, e0.y, e0.z, e0.w, e1.x, e1.y, e1.z, e1.w};
        float x[8] = {x0.x, x0.y, x0.z, x0.w, x1.x, x1.y, x1.z, x1.w};

        // hoisted ratio-table loads: i0 crosses at most one boundary per 8
        float srcA = fminf(fmaxf(((float)n0 + 0.5f) * 0.0125f - 0.5f, 0.0f), 3999.0f);
        float srcB = fminf(fmaxf(((float)(n0 + 7) + 0.5f) * 0.0125f - 0.5f, 0.0f), 3999.0f);
        const int iA = (int)floorf(srcA);
        const int iB = (int)floorf(srcB);
        const float rA0 = rb[iA], rA1 = rb[min(iA + 1, 3999)];
        const float rB0 = rb[iB], rB1 = rb[min(iB + 1, 3999)];

        float r[8], le[8], lr[8];
        float se = 0.0f, sr = 0.0f;
        #pragma unroll
        for (int j = 0; j < 8; ++j) {
            r[j] = x[j] - e[j];
            float src = fminf(fmaxf(((float)(n0 + j) + 0.5f) * 0.0125f - 0.5f, 0.0f), 3999.0f);
            float f0 = floorf(src);
            int   ij = (int)f0;
            float wj = src - f0;
            float r0 = (ij == iA) ? rA0 : rB0;
            float r1 = (ij == iA) ? rA1 : rB1;
            float ratio = r0 * (1.0f - wj) + r1 * wj;
            float ge = gain_of(e[j], 0.3f, ratio);
            float gr = gain_of(r[j], 0.1f, ratio * 0.5f);
            se = fmaf(0.9f, se, 0.1f * ge);  le[j] = se;
            sr = fmaf(0.9f, sr, 0.1f * gr);  lr[j] = sr;
        }

        float Ie = se, Ir = sr, t;
        t = __shfl_up_sync(0xffffffffu, Ie, 1);  if (lane >= 1)  Ie = fmaf(0.43046721f,            t, Ie);
        t = __shfl_up_sync(0xffffffffu, Ir, 1);  if (lane >= 1)  Ir = fmaf(0.43046721f,            t, Ir);
        t = __shfl_up_sync(0xffffffffu, Ie, 2);  if (lane >= 2)  Ie = fmaf(0.1853020188851841f,    t, Ie);
        t = __shfl_up_sync(0xffffffffu, Ir, 2);  if (lane >= 2)  Ir = fmaf(0.1853020188851841f,    t, Ir);
        t = __shfl_up_sync(0xffffffffu, Ie, 4);  if (lane >= 4)  Ie = fmaf(0.03433683820292512f,   t, Ie);
        t = __shfl_up_sync(0xffffffffu, Ir, 4);  if (lane >= 4)  Ir = fmaf(0.03433683820292512f,   t, Ir);
        t = __shfl_up_sync(0xffffffffu, Ie, 8);  if (lane >= 8)  Ie = fmaf(0.001179018457773862f,  t, Ie);
        t = __shfl_up_sync(0xffffffffu, Ir, 8);  if (lane >= 8)  Ir = fmaf(0.001179018457773862f,  t, Ir);
        t = __shfl_up_sync(0xffffffffu, Ie, 16); if (lane >= 16) Ie = fmaf(1.390084523771456e-06f, t, Ie);
        t = __shfl_up_sync(0xffffffffu, Ir, 16); if (lane >= 16) Ir = fmaf(1.390084523771456e-06f, t, Ir);

        float ce = __shfl_up_sync(0xffffffffu, Ie, 1); if (lane == 0) ce = 0.0f;
        float cr = __shfl_up_sync(0xffffffffu, Ir, 1); if (lane == 0) cr = 0.0f;
        ce = fmaf(qi, s_in_e, ce);
        cr = fmaf(qi, s_in_r, cr);

        float Ie31 = __shfl_sync(0xffffffffu, Ie, 31);
        float Ir31 = __shfl_sync(0xffffffffu, Ir, 31);
        s_in_e = fmaf(q32, s_in_e, Ie31);
        s_in_r = fmaf(q32, s_in_r, Ir31);

        if (g0 >= t0) {
            const float d[8] = {0.9f, 0.81f, 0.729f, 0.6561f,
                                0.59049f, 0.531441f, 0.4782969f, 0.43046721f};
            float* so = &s_o[wcta][n0 - t0];
            #pragma unroll
            for (int j = 0; j < 8; ++j) {
                float sej = fmaf(d[j], ce, le[j]);
                float srj = fmaf(d[j], cr, lr[j]);
                float o = fmaf(sej, e[j], 0.1f * (srj * r[j]));
                so[j] = o;
                mx_out = fmaxf(mx_out, fabsf(o));
                mx_enh = fmaxf(mx_enh, fabsf(e[j]));
            }
        }
    }

    #pragma unroll
    for (int off = 16; off > 0; off >>= 1) {
        mx_out = fmaxf(mx_out, __shfl_xor_sync(0xffffffffu, mx_out, off));
        mx_enh = fmaxf(mx_enh, __shfl_xor_sync(0xffffffffu, mx_enh, off));
    }
    if (lane == 0) {
        atomicMax(&g_max_out_i, __float_as_int(mx_out));
        atomicMax(&g_max_enh_i, __float_as_int(mx_enh));
    }

    // ---- device-wide arrive + spin barrier (all 500 CTAs resident) ----
    __syncthreads();
    if (threadIdx.x == 0) {
        __threadfence();
        atomicAdd(&g_done, 1u);
        while (*(volatile unsigned*)&g_done < (unsigned)gridDim.x)
            __nanosleep(64);
    }
    __syncthreads();

    // ---- scale from smem, single gmem write ----
    {
        const float mo = __int_as_float(*(volatile int*)&g_max_out_i);
        const float me = __int_as_float(*(volatile int*)&g_max_enh_i);
        const float s  = __fdividef(me, mo + 1e-8f);
        #pragma unroll 1
        for (int off = lane * 8; off < CCHUNK; off += 256) {
            const float* so = &s_o[wcta][off];
            float4 v0 = make_float4(so[0] * s, so[1] * s, so[2] * s, so[3] * s);
            float4 v1 = make_float4(so[4] * s, so[5] * s, so[6] * s, so[7] * s);
            *(float4*)(ob + t0 + off)     = v0;
            *(float4*)(ob + t0 + off + 4) = v1;
        }
    }
}

// =====================================================================
extern "C" void kernel_launch(void* const* d_in, const int* in_sizes, int n_in,
                              void* d_out, int out_size)
{
    const float* gru   = (const float*)d_in[0];
    const float* enh   = (const float*)d_in[1];
    const float* noisy = (const float*)d_in[2];
    const float* W1    = (const float*)d_in[3];
    const float* b1    = (const float*)d_in[4];
    const float* a1    = (const float*)d_in[5];
    const float* W2    = (const float*)d_in[6];
    const float* b2    = (const float*)d_in[7];
    const float* a2    = (const float*)d_in[8];
    const float* W3    = (const float*)d_in[9];
    const float* b3    = (const float*)d_in[10];
    float* out = (float*)d_out;

    cudaFuncSetAttribute(mlp_mma_kernel, cudaFuncAttributeMaxDynamicSharedMemorySize, MLP_SMEM);

    prep_kernel<<<40, 256>>>(W1, W2);
    mlp_mma_kernel<<<M_ / TOK, 512, MLP_SMEM>>>(gru, b1, a1, b2, a2, W3, b3);
    compress_kernel<<<CGRID, 256>>>(enh, noisy, out);
}

// round 17
// speedup vs baseline: 1.3344x; 1.1051x over previous
#include <cuda_runtime.h>
#include <cuda_fp16.h>
#include <math.h>
#include <stdint.h>

// ---------------- problem constants ----------------
#define B_    16
#define T_    4000
#define GRUH  256
#define H1_   128
#define H2_   64
#define N_    320000          // T_ * HOP(80)
#define M_    (B_ * T_)       // 64000 tokens

// ---------------- device scratch ----------------
__device__ float g_ratio[M_];
__device__ int   g_max_out_i;
__device__ int   g_max_enh_i;
__device__ unsigned g_done;
__device__ uint4 g_w1q[128 * 68];   // W1 fp16 hi/lo granules
__device__ uint4 g_w2q[64 * 36];    // W2 fp16 hi/lo granules

// =====================================================================
// helpers (fp16)
// =====================================================================
__device__ __forceinline__ uint32_t pack_h2(__half a, __half b) {
    return (uint32_t)__half_as_ushort(a) | ((uint32_t)__half_as_ushort(b) << 16);
}
__device__ __forceinline__ uint32_t cvt2h(float2 v) {
    return pack_h2(__float2half_rn(v.x), __float2half_rn(v.y));
}
__device__ __forceinline__ void split2h(float v0, float v1, uint32_t& hi, uint32_t& lo) {
    __half h0 = __float2half_rn(v0);
    __half h1 = __float2half_rn(v1);
    float l0 = v0 - __half2float(h0);
    float l1 = v1 - __half2float(h1);
    hi = pack_h2(h0, h1);
    lo = pack_h2(__float2half_rn(l0), __float2half_rn(l1));
}
// m16n8k16 fp16 MMA, f32 accumulate (portable PTX, sm_80+)
__device__ __forceinline__ void mma_f16_(float c[4], const uint32_t a[4],
                                         uint32_t b0, uint32_t b1) {
    asm volatile(
        "mma.sync.aligned.m16n8k16.row.col.f32.f16.f16.f32 "
        "{%0,%1,%2,%3}, {%4,%5,%6,%7}, {%8,%9}, {%0,%1,%2,%3};"
        : "+f"(c[0]), "+f"(c[1]), "+f"(c[2]), "+f"(c[3])
        : "r"(a[0]), "r"(a[1]), "r"(a[2]), "r"(a[3]), "r"(b0), "r"(b1));
}
#define MMA(c, a, b0, b1) mma_f16_(c, a, b0, b1)

#define W1_GSTRIDE 68
#define W2_GSTRIDE 36
#define H1_WSTRIDE 68

// =====================================================================
// Kernel P: one-time weight conversion — 40 CTAs, one granule/thread
// =====================================================================
__global__ __launch_bounds__(256)
void prep_kernel(const float* __restrict__ W1, const float* __restrict__ W2)
{
    const int tid = threadIdx.x;
    const int bid = blockIdx.x;
    if (bid < 32) {
        const int gid = bid * 256 + tid;       // 0..8191
        const int row = gid >> 6;              // 0..127
        const int pos = gid & 63;
        const int kt = pos >> 2, sub = pos & 3;
        const float* src = W1 + (size_t)row * GRUH + kt * 16 + sub * 2;
        float2 fa = *(const float2*)(src);
        float2 fb = *(const float2*)(src + 8);
        uint32_t ha, la, hb, lb;
        split2h(fa.x, fa.y, ha, la);
        split2h(fb.x, fb.y, hb, lb);
        g_w1q[row * W1_GSTRIDE + kt * 4 + sub] = make_uint4(ha, hb, la, lb);
    } else {
        const int gid = (bid - 32) * 256 + tid; // 0..2047
        const int row = gid >> 5;               // 0..63
        const int pos = gid & 31;
        const int kt = pos >> 2, sub = pos & 3;
        const float* src = W2 + (size_t)row * H1_ + kt * 16 + sub * 2;
        float2 fa = *(const float2*)(src);
        float2 fb = *(const float2*)(src + 8);
        uint32_t ha, la, hb, lb;
        split2h(fa.x, fa.y, ha, la);
        split2h(fb.x, fb.y, hb, lb);
        g_w2q[row * W2_GSTRIDE + kt * 4 + sub] = make_uint4(ha, hb, la, lb);
        if (bid == 39 && tid == 0) { g_done = 0u; g_max_out_i = 0; g_max_enh_i = 0; }
    }
}

// =====================================================================
// Kernel A: fp16 MLP via mma.sync -> ratio[m]
//   GEMM1: 2-term (A single fp16, B hi/lo) — error = eps_fp16 ≈ 4.9e-4.
//   GEMM2: 3-term (H1 hi/lo, W2 hi/lo) — negligible error.
//   256 tokens/CTA, 250 CTAs, 512 threads.
// =====================================================================
#define TOK 256

#define SO_W2Q  0
#define SO_B1   36864
#define SO_B2   37376
#define SO_W3   37632
#define SO_SC   37888
#define SO_W1Q  38016
#define SO_H1H  38016
#define SO_H1L  107648
#define MLP_SMEM 177280

struct XB { float2 c00, c10, c20, c30, c01, c11, c21, c31; };

__device__ __forceinline__ void loadx(XB& x,
        const float* xr0, const float* xr8,
        const float* xr16, const float* xr24, int k0)
{
    x.c00 = *(const float2*)(xr0  + k0);  x.c01 = *(const float2*)(xr0  + k0 + 8);
    x.c10 = *(const float2*)(xr8  + k0);  x.c11 = *(const float2*)(xr8  + k0 + 8);
    x.c20 = *(const float2*)(xr16 + k0);  x.c21 = *(const float2*)(xr16 + k0 + 8);
    x.c30 = *(const float2*)(xr24 + k0);  x.c31 = *(const float2*)(xr24 + k0 + 8);
}

__device__ __forceinline__ void g1_step(XB& x, float acc[2][8][4],
        const uint4* w1q, int warp_n0, int tig, int kt, int ktn,
        const float* xr0, const float* xr8,
        const float* xr16, const float* xr24)
{
    uint32_t a0[4], a1[4];
    a0[0] = cvt2h(x.c00);
    a0[1] = cvt2h(x.c10);
    a0[2] = cvt2h(x.c01);
    a0[3] = cvt2h(x.c11);
    a1[0] = cvt2h(x.c20);
    a1[1] = cvt2h(x.c30);
    a1[2] = cvt2h(x.c21);
    a1[3] = cvt2h(x.c31);

    const int kn = (ktn < 16) ? ktn : 14;
    loadx(x, xr0, xr8, xr16, xr24, kn * 16 + tig * 2);

    const uint4* p = w1q + warp_n0 * W1_GSTRIDE + kt * 4 + tig;
    #pragma unroll
    for (int nt = 0; nt < 8; ++nt) {
        uint4 g = *p;
        p += 8 * W1_GSTRIDE;
        MMA(acc[0][nt], a0, g.x, g.y);   // A * Bhi
        MMA(acc[1][nt], a1, g.x, g.y);
        MMA(acc[0][nt], a0, g.z, g.w);   // A * Blo
        MMA(acc[1][nt], a1, g.z, g.w);
    }
}

__global__ __launch_bounds__(512, 1)
void mlp_mma_kernel(const float* __restrict__ X,
                    const float* __restrict__ b1, const float* __restrict__ a1p,
                    const float* __restrict__ b2, const float* __restrict__ a2p,
                    const float* __restrict__ W3, const float* __restrict__ b3)
{
    extern __shared__ char sm[];
    const int tid  = threadIdx.x;
    const int wid  = tid >> 5;
    const int lane = tid & 31;
    const int grp  = lane >> 2;
    const int tig  = lane & 3;
    const int m0   = blockIdx.x * TOK;

    uint4* w1q = (uint4*)(sm + SO_W1Q);
    uint4* w2q = (uint4*)(sm + SO_W2Q);
    uint32_t* h1h = (uint32_t*)(sm + SO_H1H);
    uint32_t* h1l = (uint32_t*)(sm + SO_H1L);
    float* b1s = (float*)(sm + SO_B1);
    float* b2s = (float*)(sm + SO_B2);
    float* w3s = (float*)(sm + SO_W3);
    float* scl = (float*)(sm + SO_SC);

    // ---- stage biases / w3 row 2 / scalars ----
    if (tid < 128) b1s[tid] = b1[tid];
    else if (tid < 192) b2s[tid - 128] = b2[tid - 128];
    else if (tid < 256) w3s[tid - 192] = W3[2 * H2_ + (tid - 192)];
    if (tid == 0) { scl[0] = *a1p; scl[1] = *a2p; scl[2] = b3[2]; }

    // ---- copy pre-converted weight granules into smem ----
    #pragma unroll 4
    for (int i = tid; i < 128 * W1_GSTRIDE; i += 512) w1q[i] = g_w1q[i];
    #pragma unroll 2
    for (int i = tid; i < 64 * W2_GSTRIDE; i += 512) w2q[i] = g_w2q[i];
    __syncthreads();

    // ========= GEMM1: [256 x 256] * W1^T -> [256 x 128], 2-term =========
    const int wid_m  = wid >> 1;
    const int nhalf  = wid & 1;
    const int warp_n0 = nhalf * 64 + grp;
    const float* xr0  = X + (size_t)(m0 + wid_m * 32 + grp) * GRUH;
    const float* xr8  = xr0 + 8  * GRUH;
    const float* xr16 = xr0 + 16 * GRUH;
    const float* xr24 = xr0 + 24 * GRUH;

    float acc[2][8][4];
    #pragma unroll
    for (int t = 0; t < 2; ++t)
        #pragma unroll
        for (int nt = 0; nt < 8; ++nt)
            #pragma unroll
            for (int j = 0; j < 4; ++j) acc[t][nt][j] = 0.0f;

    XB xa, xb;
    loadx(xa, xr0, xr8, xr16, xr24, 0 * 16 + tig * 2);
    loadx(xb, xr0, xr8, xr16, xr24, 1 * 16 + tig * 2);

    #pragma unroll 1
    for (int kt = 0; kt < 16; kt += 2) {
        g1_step(xa, acc, w1q, warp_n0, tig, kt,     kt + 2, xr0, xr8, xr16, xr24);
        g1_step(xb, acc, w1q, warp_n0, tig, kt + 1, kt + 3, xr0, xr8, xr16, xr24);
    }
    __syncthreads();

    // ---- epilogue 1: bias + prelu, split fp16 hi/lo -> H1 smem ----
    {
        const float A1 = scl[0];
        const int rbase = wid_m * 32 + grp;
        #pragma unroll
        for (int t = 0; t < 2; ++t) {
            const int r = rbase + t * 16;
            #pragma unroll
            for (int nt = 0; nt < 8; ++nt) {
                const int col0 = nhalf * 64 + nt * 8 + tig * 2;
                float v00 = acc[t][nt][0] + b1s[col0];
                float v01 = acc[t][nt][1] + b1s[col0 + 1];
                float v80 = acc[t][nt][2] + b1s[col0];
                float v81 = acc[t][nt][3] + b1s[col0 + 1];
                v00 = (v00 >= 0.0f) ? v00 : A1 * v00;
                v01 = (v01 >= 0.0f) ? v01 : A1 * v01;
                v80 = (v80 >= 0.0f) ? v80 : A1 * v80;
                v81 = (v81 >= 0.0f) ? v81 : A1 * v81;
                uint32_t h0, l0, h8, l8;
                split2h(v00, v01, h0, l0);
                split2h(v80, v81, h8, l8);
                const int cw = nhalf * 32 + nt * 4 + tig;
                const int w0 = r * H1_WSTRIDE + cw;
                const int w8 = (r + 8) * H1_WSTRIDE + cw;
                h1h[w0] = h0; h1l[w0] = l0;
                h1h[w8] = h8; h1l[w8] = l8;
            }
        }
    }
    __syncthreads();

    // ========= GEMM2: [256 x 128] * W2^T -> [256 x 64], 3-term =========
    float acc2[8][4];
    #pragma unroll
    for (int nt = 0; nt < 8; ++nt)
        #pragma unroll
        for (int j = 0; j < 4; ++j) acc2[nt][j] = 0.0f;

    const int r0w = (wid * 16 + grp) * H1_WSTRIDE;
    const int r8w = (wid * 16 + grp + 8) * H1_WSTRIDE;

    #pragma unroll 1
    for (int kt = 0; kt < 8; ++kt) {
        const int wbase = kt * 8 + tig;
        uint32_t ah[4], al[4];
        ah[0] = h1h[r0w + wbase];     al[0] = h1l[r0w + wbase];
        ah[1] = h1h[r8w + wbase];     al[1] = h1l[r8w + wbase];
        ah[2] = h1h[r0w + wbase + 4]; al[2] = h1l[r0w + wbase + 4];
        ah[3] = h1h[r8w + wbase + 4]; al[3] = h1l[r8w + wbase + 4];
        const uint4* p = w2q + grp * W2_GSTRIDE + kt * 4 + tig;
        #pragma unroll
        for (int nt = 0; nt < 8; ++nt) {
            uint4 g = *p;
            p += 8 * W2_GSTRIDE;
            MMA(acc2[nt], ah, g.x, g.y);
            MMA(acc2[nt], ah, g.z, g.w);
            MMA(acc2[nt], al, g.x, g.y);
        }
    }

    // ---- epilogue 2: bias + prelu, dot w3, reduce over tig, softplus ----
    {
        const float A2 = scl[1];
        float p0 = 0.0f, p8 = 0.0f;
        #pragma unroll
        for (int nt = 0; nt < 8; ++nt) {
            const int col0 = nt * 8 + tig * 2;
            float v00 = acc2[nt][0] + b2s[col0];
            float v01 = acc2[nt][1] + b2s[col0 + 1];
            float v80 = acc2[nt][2] + b2s[col0];
            float v81 = acc2[nt][3] + b2s[col0 + 1];
            v00 = (v00 >= 0.0f) ? v00 : A2 * v00;
            v01 = (v01 >= 0.0f) ? v01 : A2 * v01;
            v80 = (v80 >= 0.0f) ? v80 : A2 * v80;
            v81 = (v81 >= 0.0f) ? v81 : A2 * v81;
            p0 = fmaf(v00, w3s[col0], fmaf(v01, w3s[col0 + 1], p0));
            p8 = fmaf(v80, w3s[col0], fmaf(v81, w3s[col0 + 1], p8));
        }
        p0 += __shfl_xor_sync(0xffffffffu, p0, 1);
        p0 += __shfl_xor_sync(0xffffffffu, p0, 2);
        p8 += __shfl_xor_sync(0xffffffffu, p8, 1);
        p8 += __shfl_xor_sync(0xffffffffu, p8, 2);
        if (tig == 0) {
            const float bb3 = scl[2];
            float pa = p0 + bb3;
            float pb = p8 + bb3;
            float spa = fmaxf(pa, 0.0f) + log1pf(expf(-fabsf(pa)));
            float spb = fmaxf(pb, 0.0f) + log1pf(expf(-fabsf(pb)));
            float ra = fminf(fmaxf(spa + 1.0f, 1.0f), 20.0f);
            float rb = fminf(fmaxf(spb + 1.0f, 1.0f), 20.0f);
            g_ratio[m0 + wid * 16 + grp]     = ra;
            g_ratio[m0 + wid * 16 + grp + 8] = rb;
        }
    }
}

// =====================================================================
// Kernel B: blocked IIR + fused normalize (unchanged from R15)
// =====================================================================
#define CCHUNK 1280
#define CWARM  256
#define C_PB   (N_ / CCHUNK)      // 250 chunks per batch
#define CGRID  ((B_ * C_PB) / 8)  // 500 CTAs

__device__ __forceinline__ float interp_ratio(const float* __restrict__ rb, int n)
{
    float src = ((float)n + 0.5f) * 0.0125f - 0.5f;
    src = fminf(fmaxf(src, 0.0f), 3999.0f);
    float f0 = floorf(src);
    int   i0 = (int)f0;
    int   i1 = min(i0 + 1, 3999);
    float w  = src - f0;
    return rb[i0] * (1.0f - w) + rb[i1] * w;
}
__device__ __forceinline__ float gain_of(float x, float thr, float ratio)
{
    float env = fabsf(x);
    bool  over = env > thr;
    float num = over ? fmaf(thr, ratio - 1.0f, env) : env;
    float den = over ? ratio * (env + 1e-8f) : (env + 1e-8f);
    float g = __fdividef(num, den);
    return fminf(fmaxf(g, 0.1f), 2.0f);
}

__global__ __launch_bounds__(256, 4)
void compress_kernel(const float* __restrict__ enh,
                     const float* __restrict__ noisy,
                     float* __restrict__ out)
{
    __shared__ float s_o[8][CCHUNK];   // 40 KB: per-warp chunk outputs

    const int wcta = threadIdx.x >> 5;
    const int w    = (blockIdx.x * blockDim.x + threadIdx.x) >> 5;
    const int lane = threadIdx.x & 31;
    const int b     = w / C_PB;
    const int chunk = w % C_PB;
    const int t0    = chunk * CCHUNK;
    const int start = (chunk == 0) ? 0 : (t0 - CWARM);

    const float* eb = enh   + (size_t)b * N_;
    const float* nb = noisy + (size_t)b * N_;
    float*       ob = out   + (size_t)b * N_;
    const float* rb = g_ratio + b * T_;

    const float q   = 0.43046721f;                    // 0.9^8
    const float qi  = powf(q, (float)lane);
    const float q32 = 1.9342813113834067e-12f;        // 0.9^256

    float s_in_e, s_in_r;
    {
        float e  = eb[start];
        float nn = nb[start];
        float ratio = interp_ratio(rb, start);
        s_in_e = gain_of(e, 0.3f, ratio);
        s_in_r = gain_of(nn - e, 0.1f, ratio * 0.5f);
    }

    float mx_out = 0.0f, mx_enh = 0.0f;
    const int nend = t0 + CCHUNK;

    #pragma unroll 1
    for (int g0 = start; g0 < nend; g0 += 256) {
        const int n0 = g0 + lane * 8;
        float4 e0 = *(const float4*)(eb + n0);
        float4 e1 = *(const float4*)(eb + n0 + 4);
        float4 x0 = *(const float4*)(nb + n0);
        float4 x1 = *(const float4*)(nb + n0 + 4);
        float e[8] = {e0.x, e0.y, e0.z, e0.w, e1.x, e1.y, e1.z, e1.w};
        float x[8] = {x0.x, x0.y, x0.z, x0.w, x1.x, x1.y, x1.z, x1.w};

        // hoisted ratio-table loads: i0 crosses at most one boundary per 8
        float srcA = fminf(fmaxf(((float)n0 + 0.5f) * 0.0125f - 0.5f, 0.0f), 3999.0f);
        float srcB = fminf(fmaxf(((float)(n0 + 7) + 0.5f) * 0.0125f - 0.5f, 0.0f), 3999.0f);
        const int iA = (int)floorf(srcA);
        const int iB = (int)floorf(srcB);
        const float rA0 = rb[iA], rA1 = rb[min(iA + 1, 3999)];
        const float rB0 = rb[iB], rB1 = rb[min(iB + 1, 3999)];

        float r[8], le[8], lr[8];
        float se = 0.0f, sr = 0.0f;
        #pragma unroll
        for (int j = 0; j < 8; ++j) {
            r[j] = x[j] - e[j];
            float src = fminf(fmaxf(((float)(n0 + j) + 0.5f) * 0.0125f - 0.5f, 0.0f), 3999.0f);
            float f0 = floorf(src);
            int   ij = (int)f0;
            float wj = src - f0;
            float r0 = (ij == iA) ? rA0 : rB0;
            float r1 = (ij == iA) ? rA1 : rB1;
            float ratio = r0 * (1.0f - wj) + r1 * wj;
            float ge = gain_of(e[j], 0.3f, ratio);
            float gr = gain_of(r[j], 0.1f, ratio * 0.5f);
            se = fmaf(0.9f, se, 0.1f * ge);  le[j] = se;
            sr = fmaf(0.9f, sr, 0.1f * gr);  lr[j] = sr;
        }

        float Ie = se, Ir = sr, t;
        t = __shfl_up_sync(0xffffffffu, Ie, 1);  if (lane >= 1)  Ie = fmaf(0.43046721f,            t, Ie);
        t = __shfl_up_sync(0xffffffffu, Ir, 1);  if (lane >= 1)  Ir = fmaf(0.43046721f,            t, Ir);
        t = __shfl_up_sync(0xffffffffu, Ie, 2);  if (lane >= 2)  Ie = fmaf(0.1853020188851841f,    t, Ie);
        t = __shfl_up_sync(0xffffffffu, Ir, 2);  if (lane >= 2)  Ir = fmaf(0.1853020188851841f,    t, Ir);
        t = __shfl_up_sync(0xffffffffu, Ie, 4);  if (lane >= 4)  Ie = fmaf(0.03433683820292512f,   t, Ie);
        t = __shfl_up_sync(0xffffffffu, Ir, 4);  if (lane >= 4)  Ir = fmaf(0.03433683820292512f,   t, Ir);
        t = __shfl_up_sync(0xffffffffu, Ie, 8);  if (lane >= 8)  Ie = fmaf(0.001179018457773862f,  t, Ie);
        t = __shfl_up_sync(0xffffffffu, Ir, 8);  if (lane >= 8)  Ir = fmaf(0.001179018457773862f,  t, Ir);
        t = __shfl_up_sync(0xffffffffu, Ie, 16); if (lane >= 16) Ie = fmaf(1.390084523771456e-06f, t, Ie);
        t = __shfl_up_sync(0xffffffffu, Ir, 16); if (lane >= 16) Ir = fmaf(1.390084523771456e-06f, t, Ir);

        float ce = __shfl_up_sync(0xffffffffu, Ie, 1); if (lane == 0) ce = 0.0f;
        float cr = __shfl_up_sync(0xffffffffu, Ir, 1); if (lane == 0) cr = 0.0f;
        ce = fmaf(qi, s_in_e, ce);
        cr = fmaf(qi, s_in_r, cr);

        float Ie31 = __shfl_sync(0xffffffffu, Ie, 31);
        float Ir31 = __shfl_sync(0xffffffffu, Ir, 31);
        s_in_e = fmaf(q32, s_in_e, Ie31);
        s_in_r = fmaf(q32, s_in_r, Ir31);

        if (g0 >= t0) {
            const float d[8] = {0.9f, 0.81f, 0.729f, 0.6561f,
                                0.59049f, 0.531441f, 0.4782969f, 0.43046721f};
            float* so = &s_o[wcta][n0 - t0];
            #pragma unroll
            for (int j = 0; j < 8; ++j) {
                float sej = fmaf(d[j], ce, le[j]);
                float srj = fmaf(d[j], cr, lr[j]);
                float o = fmaf(sej, e[j], 0.1f * (srj * r[j]));
                so[j] = o;
                mx_out = fmaxf(mx_out, fabsf(o));
                mx_enh = fmaxf(mx_enh, fabsf(e[j]));
            }
        }
    }

    #pragma unroll
    for (int off = 16; off > 0; off >>= 1) {
        mx_out = fmaxf(mx_out, __shfl_xor_sync(0xffffffffu, mx_out, off));
        mx_enh = fmaxf(mx_enh, __shfl_xor_sync(0xffffffffu, mx_enh, off));
    }
    if (lane == 0) {
        atomicMax(&g_max_out_i, __float_as_int(mx_out));
        atomicMax(&g_max_enh_i, __float_as_int(mx_enh));
    }

    // ---- device-wide arrive + spin barrier (all 500 CTAs resident) ----
    __syncthreads();
    if (threadIdx.x == 0) {
        __threadfence();
        atomicAdd(&g_done, 1u);
        while (*(volatile unsigned*)&g_done < (unsigned)gridDim.x)
            __nanosleep(64);
    }
    __syncthreads();

    // ---- scale from smem, single gmem write ----
    {
        const float mo = __int_as_float(*(volatile int*)&g_max_out_i);
        const float me = __int_as_float(*(volatile int*)&g_max_enh_i);
        const float s  = __fdividef(me, mo + 1e-8f);
        #pragma unroll 1
        for (int off = lane * 8; off < CCHUNK; off += 256) {
            const float* so = &s_o[wcta][off];
            float4 v0 = make_float4(so[0] * s, so[1] * s, so[2] * s, so[3] * s);
            float4 v1 = make_float4(so[4] * s, so[5] * s, so[6] * s, so[7] * s);
            *(float4*)(ob + t0 + off)     = v0;
            *(float4*)(ob + t0 + off + 4) = v1;
        }
    }
}

// =====================================================================
extern "C" void kernel_launch(void* const* d_in, const int* in_sizes, int n_in,
                              void* d_out, int out_size)
{
    const float* gru   = (const float*)d_in[0];
    const float* enh   = (const float*)d_in[1];
    const float* noisy = (const float*)d_in[2];
    const float* W1    = (const float*)d_in[3];
    const float* b1    = (const float*)d_in[4];
    const float* a1    = (const float*)d_in[5];
    const float* W2    = (const float*)d_in[6];
    const float* b2    = (const float*)d_in[7];
    const float* a2    = (const float*)d_in[8];
    const float* W3    = (const float*)d_in[9];
    const float* b3    = (const float*)d_in[10];
    float* out = (float*)d_out;

    cudaFuncSetAttribute(mlp_mma_kernel, cudaFuncAttributeMaxDynamicSharedMemorySize, MLP_SMEM);

    prep_kernel<<<40, 256>>>(W1, W2);
    mlp_mma_kernel<<<M_ / TOK, 512, MLP_SMEM>>>(gru, b1, a1, b2, a2, W3, b3);
    compress_kernel<<<CGRID, 256>>>(enh, noisy, out);
}